// round 1
// baseline (speedup 1.0000x reference)
#include <cuda_runtime.h>

#define NU 400000
#define NI 200000
#define NN 600000
#define DV 16          // float4 words per row (D=64)
#define BATCH 8192

// Scratch: two ping-pong node-embedding buffers, 600000*64 floats each (153.6 MB)
__device__ float g_bufA[(size_t)NN * 64];
__device__ float g_bufB[(size_t)NN * 64];

__global__ void zero_k(float4* __restrict__ p, int n4) {
    int i = blockIdx.x * blockDim.x + threadIdx.x;
    if (i < n4) p[i] = make_float4(0.f, 0.f, 0.f, 0.f);
}

// all_emb = concat(user_emb*user_mask, item_emb*item_mask)
__global__ void mask_k(const float4* __restrict__ ue, const float4* __restrict__ ie,
                       const int4* __restrict__ um, const int4* __restrict__ im,
                       float4* __restrict__ out) {
    int i = blockIdx.x * blockDim.x + threadIdx.x;
    if (i >= NN * DV) return;
    float4 e; int4 m;
    if (i < NU * DV) { e = ue[i]; m = um[i]; }
    else             { int j = i - NU * DV; e = ie[j]; m = im[j]; }
    float4 r;
    r.x = m.x ? e.x : 0.f;
    r.y = m.y ? e.y : 0.f;
    r.z = m.z ? e.z : 0.f;
    r.w = m.w ? e.w : 0.f;
    out[i] = r;
}

__device__ __forceinline__ void red_add4(float* a, float4 v) {
    asm volatile("red.global.add.v4.f32 [%0], {%1,%2,%3,%4};"
                 :: "l"(a), "f"(v.x), "f"(v.y), "f"(v.z), "f"(v.w) : "memory");
}

// y[row] += val * x[col] per edge; 16 threads per edge, float4 granularity
__global__ void spmm_k(const int* __restrict__ rows, const int* __restrict__ cols,
                       const float* __restrict__ vals,
                       const float4* __restrict__ x, float* __restrict__ y, int nnz) {
    int t = blockIdx.x * blockDim.x + threadIdx.x;
    int e = t >> 4;
    if (e >= nnz) return;
    int lane = t & 15;
    int r = __ldg(rows + e);
    int c = __ldg(cols + e);
    float v = __ldg(vals + e);
    float4 xv = x[(size_t)c * DV + lane];
    float4 p = make_float4(v * xv.x, v * xv.y, v * xv.z, v * xv.w);
    red_add4(y + (size_t)r * 64 + (lane << 2), p);
}

// Initialize output: acc sections 0..2 = all_emb[batch rows]; ego sections 3..5 = same value.
__global__ void init_gather_k(const float4* __restrict__ buf,
                              const int* __restrict__ users, const int* __restrict__ pos,
                              const int* __restrict__ neg, float4* __restrict__ out) {
    int i = blockIdx.x * blockDim.x + threadIdx.x;
    const int SEC = BATCH * DV;
    if (i >= 3 * SEC) return;
    int sec = i / SEC;
    int rem = i - sec * SEC;
    int b = rem >> 4;
    int row = (sec == 0) ? users[b] : (sec == 1 ? NU + pos[b] : NU + neg[b]);
    float4 v = buf[(size_t)row * DV + (rem & 15)];
    out[i] = v;             // accumulated (light_out) section
    out[3 * SEC + i] = v;   // ego section
}

// After each SpMM layer: out[acc sections] += x[batch rows]; final layer scales by 1/4.
__global__ void acc_k(const float4* __restrict__ buf,
                      const int* __restrict__ users, const int* __restrict__ pos,
                      const int* __restrict__ neg, float4* __restrict__ out, float scale) {
    int i = blockIdx.x * blockDim.x + threadIdx.x;
    const int SEC = BATCH * DV;
    if (i >= 3 * SEC) return;
    int sec = i / SEC;
    int rem = i - sec * SEC;
    int b = rem >> 4;
    int row = (sec == 0) ? users[b] : (sec == 1 ? NU + pos[b] : NU + neg[b]);
    float4 v = buf[(size_t)row * DV + (rem & 15)];
    float4 o = out[i];
    o.x = (o.x + v.x) * scale;
    o.y = (o.y + v.y) * scale;
    o.z = (o.z + v.z) * scale;
    o.w = (o.w + v.w) * scale;
    out[i] = o;
}

extern "C" void kernel_launch(void* const* d_in, const int* in_sizes, int n_in,
                              void* d_out, int out_size) {
    const float* ue   = (const float*)d_in[0];
    const float* ie   = (const float*)d_in[1];
    const int*   um   = (const int*)  d_in[2];
    const int*   im   = (const int*)  d_in[3];
    const int*   rows = (const int*)  d_in[4];
    const int*   cols = (const int*)  d_in[5];
    const float* vals = (const float*)d_in[6];
    const int*   users= (const int*)  d_in[7];
    const int*   pos  = (const int*)  d_in[8];
    const int*   neg  = (const int*)  d_in[9];
    int nnz = in_sizes[4];
    float* out = (float*)d_out;

    float *bufA, *bufB;
    cudaGetSymbolAddress((void**)&bufA, g_bufA);
    cudaGetSymbolAddress((void**)&bufB, g_bufB);

    const int TPB = 256;
    const int n4 = NN * DV;                       // 9.6M float4
    const int nodeBlocks = (n4 + TPB - 1) / TPB;
    const int gBlocks = (3 * BATCH * DV + TPB - 1) / TPB;
    const long long st = (long long)nnz * 16;
    const int sBlocks = (int)((st + TPB - 1) / TPB);

    mask_k<<<nodeBlocks, TPB>>>((const float4*)ue, (const float4*)ie,
                                (const int4*)um, (const int4*)im, (float4*)bufA);
    init_gather_k<<<gBlocks, TPB>>>((const float4*)bufA, users, pos, neg, (float4*)out);

    float* src = bufA;
    float* dst = bufB;
    for (int l = 0; l < 3; l++) {
        zero_k<<<nodeBlocks, TPB>>>((float4*)dst, n4);
        spmm_k<<<sBlocks, TPB>>>(rows, cols, vals, (const float4*)src, dst, nnz);
        acc_k<<<gBlocks, TPB>>>((const float4*)dst, users, pos, neg, (float4*)out,
                                (l == 2) ? 0.25f : 1.0f);
        float* t = src; src = dst; dst = t;
    }
}

// round 2
// speedup vs baseline: 1.1513x; 1.1513x over previous
#include <cuda_runtime.h>
#include <cstdint>

#define NU 400000
#define NI 200000
#define NN 600000
#define DV 16          // float4 words per row (D=64)
#define BATCH 8192

// Scratch: two ping-pong node-embedding buffers (153.6 MB each) + frontier flags
__device__ float g_bufA[(size_t)NN * 64];
__device__ float g_bufB[(size_t)NN * 64];
__device__ unsigned char g_flags[4 * NN];   // levels 0..3

// Seed all 4 flag levels with the batch rows (these rows are read at every level)
__global__ void seed_k(const int* __restrict__ users, const int* __restrict__ pos,
                       const int* __restrict__ neg, unsigned char* __restrict__ f) {
    int i = blockIdx.x * blockDim.x + threadIdx.x;
    if (i >= 3 * BATCH) return;
    int b = i % BATCH, sec = i / BATCH;
    int row = (sec == 0) ? users[b] : (sec == 1 ? NU + pos[b] : NU + neg[b]);
    f[0 * NN + row] = 1;
    f[1 * NN + row] = 1;
    f[2 * NN + row] = 1;
    f[3 * NN + row] = 1;
}

// fout[col] |= fin[row] over all edges (one frontier hop, in-neighbors)
__global__ void flag_pass_k(const int* __restrict__ rows, const int* __restrict__ cols,
                            const unsigned char* __restrict__ fin,
                            unsigned char* __restrict__ fout, int nnz) {
    int e = blockIdx.x * blockDim.x + threadIdx.x;
    if (e >= nnz) return;
    if (fin[rows[e]]) fout[cols[e]] = 1;
}

// Masked embedding, only for flagged (level-0) rows
__global__ void mask_k(const float4* __restrict__ ue, const float4* __restrict__ ie,
                       const int4* __restrict__ um, const int4* __restrict__ im,
                       const unsigned char* __restrict__ f0, float4* __restrict__ out) {
    int t = blockIdx.x * blockDim.x + threadIdx.x;
    int r = t >> 4;
    if (r >= NN || !f0[r]) return;
    int lane = t & 15;
    int i = r * DV + lane;
    float4 e; int4 m;
    if (r < NU) { e = ue[i]; m = um[i]; }
    else        { int j = i - NU * DV; e = ie[j]; m = im[j]; }
    float4 v;
    v.x = m.x ? e.x : 0.f;
    v.y = m.y ? e.y : 0.f;
    v.z = m.z ? e.z : 0.f;
    v.w = m.w ? e.w : 0.f;
    out[i] = v;
}

// Zero only flagged destination rows
__global__ void zero_rows_k(float4* __restrict__ y, const unsigned char* __restrict__ f) {
    int t = blockIdx.x * blockDim.x + threadIdx.x;
    int r = t >> 4;
    if (r >= NN || !f[r]) return;
    y[r * DV + (t & 15)] = make_float4(0.f, 0.f, 0.f, 0.f);
}

__device__ __forceinline__ void red_add4(float* a, float4 v) {
    asm volatile("red.global.add.v4.f32 [%0], {%1,%2,%3,%4};"
                 :: "l"(a), "f"(v.x), "f"(v.y), "f"(v.z), "f"(v.w) : "memory");
}

// y[row] += val * x[col] for edges whose destination row is flagged
__global__ void spmm_k(const int* __restrict__ rows, const int* __restrict__ cols,
                       const float* __restrict__ vals,
                       const unsigned char* __restrict__ f,
                       const float4* __restrict__ x, float* __restrict__ y, int nnz) {
    int t = blockIdx.x * blockDim.x + threadIdx.x;
    int e = t >> 4;
    if (e >= nnz) return;
    int r = __ldg(rows + e);
    if (!f[r]) return;
    int lane = t & 15;
    int c = __ldg(cols + e);
    float v = __ldg(vals + e);
    float4 xv = x[(size_t)c * DV + lane];
    float4 p = make_float4(v * xv.x, v * xv.y, v * xv.z, v * xv.w);
    red_add4(y + (size_t)r * 64 + (lane << 2), p);
}

// Init output: acc sections 0..2 = x0[batch rows]; ego sections 3..5 = same value
__global__ void init_gather_k(const float4* __restrict__ buf,
                              const int* __restrict__ users, const int* __restrict__ pos,
                              const int* __restrict__ neg, float4* __restrict__ out) {
    int i = blockIdx.x * blockDim.x + threadIdx.x;
    const int SEC = BATCH * DV;
    if (i >= 3 * SEC) return;
    int sec = i / SEC;
    int rem = i - sec * SEC;
    int b = rem >> 4;
    int row = (sec == 0) ? users[b] : (sec == 1 ? NU + pos[b] : NU + neg[b]);
    float4 v = buf[(size_t)row * DV + (rem & 15)];
    out[i] = v;
    out[3 * SEC + i] = v;
}

// After each layer: out[acc sections] += x[batch rows]; last layer scales by 1/4
__global__ void acc_k(const float4* __restrict__ buf,
                      const int* __restrict__ users, const int* __restrict__ pos,
                      const int* __restrict__ neg, float4* __restrict__ out, float scale) {
    int i = blockIdx.x * blockDim.x + threadIdx.x;
    const int SEC = BATCH * DV;
    if (i >= 3 * SEC) return;
    int sec = i / SEC;
    int rem = i - sec * SEC;
    int b = rem >> 4;
    int row = (sec == 0) ? users[b] : (sec == 1 ? NU + pos[b] : NU + neg[b]);
    float4 v = buf[(size_t)row * DV + (rem & 15)];
    float4 o = out[i];
    o.x = (o.x + v.x) * scale;
    o.y = (o.y + v.y) * scale;
    o.z = (o.z + v.z) * scale;
    o.w = (o.w + v.w) * scale;
    out[i] = o;
}

extern "C" void kernel_launch(void* const* d_in, const int* in_sizes, int n_in,
                              void* d_out, int out_size) {
    const float* ue   = (const float*)d_in[0];
    const float* ie   = (const float*)d_in[1];
    const int*   um   = (const int*)  d_in[2];
    const int*   im   = (const int*)  d_in[3];
    const int*   rows = (const int*)  d_in[4];
    const int*   cols = (const int*)  d_in[5];
    const float* vals = (const float*)d_in[6];
    const int*   users= (const int*)  d_in[7];
    const int*   pos  = (const int*)  d_in[8];
    const int*   neg  = (const int*)  d_in[9];
    int nnz = in_sizes[4];
    float* out = (float*)d_out;

    float *bufA, *bufB;
    unsigned char* flags;
    cudaGetSymbolAddress((void**)&bufA, g_bufA);
    cudaGetSymbolAddress((void**)&bufB, g_bufB);
    cudaGetSymbolAddress((void**)&flags, g_flags);

    const int TPB = 256;
    const int rowThreads = NN * DV;                               // 9.6M
    const int rowBlocks = (rowThreads + TPB - 1) / TPB;
    const int gBlocks = (3 * BATCH * DV + TPB - 1) / TPB;
    const int eBlocks = (nnz + TPB - 1) / TPB;
    const long long st = (long long)nnz * 16;
    const int sBlocks = (int)((st + TPB - 1) / TPB);
    const int seedBlocks = (3 * BATCH + TPB - 1) / TPB;

    unsigned char* f0 = flags;
    unsigned char* f1 = flags + NN;
    unsigned char* f2 = flags + 2 * NN;
    unsigned char* f3 = flags + 3 * NN;

    // --- frontier computation (backwards from batch rows) ---
    cudaMemsetAsync(flags, 0, 4 * NN);
    seed_k<<<seedBlocks, TPB>>>(users, pos, neg, flags);
    flag_pass_k<<<eBlocks, TPB>>>(rows, cols, f3, f2, nnz);   // N2 = nbrs(N3) ∪ batch
    flag_pass_k<<<eBlocks, TPB>>>(rows, cols, f2, f1, nnz);   // N1 = nbrs(N2) ∪ batch
    flag_pass_k<<<eBlocks, TPB>>>(rows, cols, f1, f0, nnz);   // N0 = nbrs(N1) ∪ batch

    // --- x0: masked embeddings at N0 rows only ---
    mask_k<<<rowBlocks, TPB>>>((const float4*)ue, (const float4*)ie,
                               (const int4*)um, (const int4*)im, f0, (float4*)bufA);
    init_gather_k<<<gBlocks, TPB>>>((const float4*)bufA, users, pos, neg, (float4*)out);

    // --- 3 frontier-restricted SpMM layers ---
    float* src = bufA;
    float* dst = bufB;
    unsigned char* lf[3] = { f1, f2, f3 };
    for (int l = 0; l < 3; l++) {
        zero_rows_k<<<rowBlocks, TPB>>>((float4*)dst, lf[l]);
        spmm_k<<<sBlocks, TPB>>>(rows, cols, vals, lf[l], (const float4*)src, dst, nnz);
        acc_k<<<gBlocks, TPB>>>((const float4*)dst, users, pos, neg, (float4*)out,
                                (l == 2) ? 0.25f : 1.0f);
        float* t = src; src = dst; dst = t;
    }
}

// round 3
// speedup vs baseline: 1.9088x; 1.6579x over previous
#include <cuda_runtime.h>
#include <cstdint>

#define NU 400000
#define NI 200000
#define NN 600000
#define MAXNNZ 1200000
#define DV 16          // float4 words per row (D=64)
#define BATCH 8192

#define SCAN_TPB 256
#define SCAN_ITEMS 4
#define SCAN_CHUNK (SCAN_TPB * SCAN_ITEMS)      // 1024
#define NB_SCAN ((NN + SCAN_CHUNK - 1) / SCAN_CHUNK)  // 586

// ---- scratch (device globals; allocation is forbidden) ----
__device__ float g_bufA[(size_t)NN * 64];
__device__ float g_bufB[(size_t)NN * 64];
__device__ int   g_deg[NN];
__device__ int   g_rowptr[NN];
__device__ int   g_wpos[NN];
__device__ int   g_scol[MAXNNZ];
__device__ float g_sval[MAXNNZ];
__device__ unsigned char g_flags[4 * NN];
__device__ int   g_lists[4 * NN];
__device__ int   g_cnt[4];
__device__ int   g_bsums[NB_SCAN];

// ================= CSR build =================
__global__ void hist_k(const int* __restrict__ rows, int* __restrict__ deg, int nnz) {
    int e = blockIdx.x * blockDim.x + threadIdx.x;
    if (e < nnz) atomicAdd(&deg[rows[e]], 1);
}

__global__ void scan1_k(const int* __restrict__ deg, int* __restrict__ out,
                        int* __restrict__ bsums) {
    __shared__ int sh[SCAN_TPB];
    int base = blockIdx.x * SCAN_CHUNK + threadIdx.x * SCAN_ITEMS;
    int v[SCAN_ITEMS]; int s = 0;
#pragma unroll
    for (int k = 0; k < SCAN_ITEMS; k++) {
        int idx = base + k;
        v[k] = (idx < NN) ? deg[idx] : 0;
        s += v[k];
    }
    sh[threadIdx.x] = s; __syncthreads();
    for (int off = 1; off < SCAN_TPB; off <<= 1) {
        int t = (threadIdx.x >= off) ? sh[threadIdx.x - off] : 0;
        __syncthreads();
        sh[threadIdx.x] += t;
        __syncthreads();
    }
    int excl = sh[threadIdx.x] - s;
    if (threadIdx.x == SCAN_TPB - 1) bsums[blockIdx.x] = sh[SCAN_TPB - 1];
    int run = excl;
#pragma unroll
    for (int k = 0; k < SCAN_ITEMS; k++) {
        int idx = base + k;
        if (idx < NN) out[idx] = run;
        run += v[k];
    }
}

__global__ void scan2_k(int* __restrict__ bsums) {
    __shared__ int sh[1024];
    int v = (threadIdx.x < NB_SCAN) ? bsums[threadIdx.x] : 0;
    sh[threadIdx.x] = v; __syncthreads();
    for (int off = 1; off < 1024; off <<= 1) {
        int t = (threadIdx.x >= off) ? sh[threadIdx.x - off] : 0;
        __syncthreads();
        sh[threadIdx.x] += t;
        __syncthreads();
    }
    if (threadIdx.x < NB_SCAN) bsums[threadIdx.x] = sh[threadIdx.x] - v;  // exclusive
}

__global__ void scan3_k(int* __restrict__ out, const int* __restrict__ bsums) {
    int idx = blockIdx.x * blockDim.x + threadIdx.x;
    if (idx < NN) out[idx] += bsums[idx / SCAN_CHUNK];
}

__global__ void scatter_k(const int* __restrict__ rows, const int* __restrict__ cols,
                          const float* __restrict__ vals,
                          const int* __restrict__ rowptr, int* __restrict__ wpos,
                          int* __restrict__ scol, float* __restrict__ sval, int nnz) {
    int e = blockIdx.x * blockDim.x + threadIdx.x;
    if (e >= nnz) return;
    int r = rows[e];
    int p = rowptr[r] + atomicAdd(&wpos[r], 1);
    scol[p] = cols[e];
    sval[p] = vals[e];
}

// ================= frontier =================
__global__ void seed_k(const int* __restrict__ users, const int* __restrict__ pos,
                       const int* __restrict__ neg, unsigned char* __restrict__ f) {
    int i = blockIdx.x * blockDim.x + threadIdx.x;
    if (i >= 3 * BATCH) return;
    int b = i % BATCH, sec = i / BATCH;
    int row = (sec == 0) ? users[b] : (sec == 1 ? NU + pos[b] : NU + neg[b]);
    f[0 * NN + row] = 1;
    f[1 * NN + row] = 1;
    f[2 * NN + row] = 1;
    f[3 * NN + row] = 1;
}

__global__ void compact_k(const unsigned char* __restrict__ f, int* __restrict__ list,
                          int* __restrict__ cnt) {
    int r = blockIdx.x * blockDim.x + threadIdx.x;
    if (r < NN && f[r]) list[atomicAdd(cnt, 1)] = r;
}

// mark in-neighbors (cols) of every row in list
__global__ void flag_nbrs_k(const int* __restrict__ list, const int* __restrict__ cntp,
                            const int* __restrict__ rowptr, const int* __restrict__ deg,
                            const int* __restrict__ scol, unsigned char* __restrict__ fout) {
    int n = *cntp;
    for (int i = blockIdx.x * blockDim.x + threadIdx.x; i < n;
         i += gridDim.x * blockDim.x) {
        int r = list[i];
        int s = rowptr[r], e = s + deg[r];
        for (int j = s; j < e; j++) fout[scol[j]] = 1;
    }
}

// ================= compute =================
__global__ void mask_list_k(const float4* __restrict__ ue, const float4* __restrict__ ie,
                            const int4* __restrict__ um, const int4* __restrict__ im,
                            const int* __restrict__ list, const int* __restrict__ cntp,
                            float4* __restrict__ out) {
    int n16 = (*cntp) * DV;
    for (int t = blockIdx.x * blockDim.x + threadIdx.x; t < n16;
         t += gridDim.x * blockDim.x) {
        int r = list[t >> 4];
        int lane = t & 15;
        int i = r * DV + lane;
        float4 e; int4 m;
        if (r < NU) { e = ue[i]; m = um[i]; }
        else        { int j = i - NU * DV; e = ie[j]; m = im[j]; }
        float4 v;
        v.x = m.x ? e.x : 0.f;
        v.y = m.y ? e.y : 0.f;
        v.z = m.z ? e.z : 0.f;
        v.w = m.w ? e.w : 0.f;
        out[i] = v;
    }
}

// CSR row-gather SpMM over a compacted row list; no atomics, writes each row once
__global__ void spmm_csr_k(const int* __restrict__ list, const int* __restrict__ cntp,
                           const int* __restrict__ rowptr, const int* __restrict__ deg,
                           const int* __restrict__ scol, const float* __restrict__ sval,
                           const float4* __restrict__ x, float4* __restrict__ y) {
    int n16 = (*cntp) * DV;
    for (int t = blockIdx.x * blockDim.x + threadIdx.x; t < n16;
         t += gridDim.x * blockDim.x) {
        int r = list[t >> 4];
        int lane = t & 15;
        int s = rowptr[r], e = s + deg[r];
        float4 acc = make_float4(0.f, 0.f, 0.f, 0.f);
        for (int j = s; j < e; j++) {
            int c = __ldg(scol + j);
            float v = __ldg(sval + j);
            float4 xv = x[(size_t)c * DV + lane];
            acc.x += v * xv.x;
            acc.y += v * xv.y;
            acc.z += v * xv.z;
            acc.w += v * xv.w;
        }
        y[(size_t)r * DV + lane] = acc;
    }
}

// ================= output gathers =================
__global__ void init_gather_k(const float4* __restrict__ buf,
                              const int* __restrict__ users, const int* __restrict__ pos,
                              const int* __restrict__ neg, float4* __restrict__ out) {
    int i = blockIdx.x * blockDim.x + threadIdx.x;
    const int SEC = BATCH * DV;
    if (i >= 3 * SEC) return;
    int sec = i / SEC;
    int rem = i - sec * SEC;
    int b = rem >> 4;
    int row = (sec == 0) ? users[b] : (sec == 1 ? NU + pos[b] : NU + neg[b]);
    float4 v = buf[(size_t)row * DV + (rem & 15)];
    out[i] = v;
    out[3 * SEC + i] = v;
}

__global__ void acc_k(const float4* __restrict__ buf,
                      const int* __restrict__ users, const int* __restrict__ pos,
                      const int* __restrict__ neg, float4* __restrict__ out, float scale) {
    int i = blockIdx.x * blockDim.x + threadIdx.x;
    const int SEC = BATCH * DV;
    if (i >= 3 * SEC) return;
    int sec = i / SEC;
    int rem = i - sec * SEC;
    int b = rem >> 4;
    int row = (sec == 0) ? users[b] : (sec == 1 ? NU + pos[b] : NU + neg[b]);
    float4 v = buf[(size_t)row * DV + (rem & 15)];
    float4 o = out[i];
    o.x = (o.x + v.x) * scale;
    o.y = (o.y + v.y) * scale;
    o.z = (o.z + v.z) * scale;
    o.w = (o.w + v.w) * scale;
    out[i] = o;
}

extern "C" void kernel_launch(void* const* d_in, const int* in_sizes, int n_in,
                              void* d_out, int out_size) {
    const float* ue   = (const float*)d_in[0];
    const float* ie   = (const float*)d_in[1];
    const int*   um   = (const int*)  d_in[2];
    const int*   im   = (const int*)  d_in[3];
    const int*   rows = (const int*)  d_in[4];
    const int*   cols = (const int*)  d_in[5];
    const float* vals = (const float*)d_in[6];
    const int*   users= (const int*)  d_in[7];
    const int*   pos  = (const int*)  d_in[8];
    const int*   neg  = (const int*)  d_in[9];
    int nnz = in_sizes[4];
    float* out = (float*)d_out;

    float *bufA, *bufB, *sval;
    int *deg, *rowptr, *wpos, *scol, *lists, *cnt, *bsums;
    unsigned char* flags;
    cudaGetSymbolAddress((void**)&bufA, g_bufA);
    cudaGetSymbolAddress((void**)&bufB, g_bufB);
    cudaGetSymbolAddress((void**)&deg, g_deg);
    cudaGetSymbolAddress((void**)&rowptr, g_rowptr);
    cudaGetSymbolAddress((void**)&wpos, g_wpos);
    cudaGetSymbolAddress((void**)&scol, g_scol);
    cudaGetSymbolAddress((void**)&sval, g_sval);
    cudaGetSymbolAddress((void**)&flags, g_flags);
    cudaGetSymbolAddress((void**)&lists, g_lists);
    cudaGetSymbolAddress((void**)&cnt, g_cnt);
    cudaGetSymbolAddress((void**)&bsums, g_bsums);

    const int TPB = 256;
    const int eBlocks = (nnz + TPB - 1) / TPB;
    const int nBlocks = (NN + TPB - 1) / TPB;
    const int gBlocks = (3 * BATCH * DV + TPB - 1) / TPB;
    const int seedBlocks = (3 * BATCH + TPB - 1) / TPB;
    const int GS = 4096;   // grid-stride kernels

    // --- zero counters/flags ---
    cudaMemsetAsync(deg, 0, NN * sizeof(int));
    cudaMemsetAsync(wpos, 0, NN * sizeof(int));
    cudaMemsetAsync(flags, 0, 4 * NN);
    cudaMemsetAsync(cnt, 0, 4 * sizeof(int));

    // --- CSR build ---
    hist_k<<<eBlocks, TPB>>>(rows, deg, nnz);
    scan1_k<<<NB_SCAN, SCAN_TPB>>>(deg, rowptr, bsums);
    scan2_k<<<1, 1024>>>(bsums);
    scan3_k<<<nBlocks, TPB>>>(rowptr, bsums);
    scatter_k<<<eBlocks, TPB>>>(rows, cols, vals, rowptr, wpos, scol, sval, nnz);

    // --- frontiers (backwards from batch rows) ---
    seed_k<<<seedBlocks, TPB>>>(users, pos, neg, flags);
    compact_k<<<nBlocks, TPB>>>(flags + 3 * NN, lists + 3 * NN, cnt + 3);
    flag_nbrs_k<<<GS, TPB>>>(lists + 3 * NN, cnt + 3, rowptr, deg, scol, flags + 2 * NN);
    compact_k<<<nBlocks, TPB>>>(flags + 2 * NN, lists + 2 * NN, cnt + 2);
    flag_nbrs_k<<<GS, TPB>>>(lists + 2 * NN, cnt + 2, rowptr, deg, scol, flags + 1 * NN);
    compact_k<<<nBlocks, TPB>>>(flags + 1 * NN, lists + 1 * NN, cnt + 1);
    flag_nbrs_k<<<GS, TPB>>>(lists + 1 * NN, cnt + 1, rowptr, deg, scol, flags);
    compact_k<<<nBlocks, TPB>>>(flags, lists, cnt);

    // --- x0 masked embeddings on N0 rows ---
    mask_list_k<<<GS, TPB>>>((const float4*)ue, (const float4*)ie,
                             (const int4*)um, (const int4*)im,
                             lists, cnt, (float4*)bufA);
    init_gather_k<<<gBlocks, TPB>>>((const float4*)bufA, users, pos, neg, (float4*)out);

    // --- 3 CSR SpMM layers over shrinking frontiers ---
    float* src = bufA;
    float* dst = bufB;
    for (int l = 0; l < 3; l++) {
        int lvl = l + 1;
        spmm_csr_k<<<GS, TPB>>>(lists + lvl * NN, cnt + lvl, rowptr, deg, scol, sval,
                                (const float4*)src, (float4*)dst);
        acc_k<<<gBlocks, TPB>>>((const float4*)dst, users, pos, neg, (float4*)out,
                                (l == 2) ? 0.25f : 1.0f);
        float* t = src; src = dst; dst = t;
    }
}

// round 4
// speedup vs baseline: 2.1847x; 1.1445x over previous
#include <cuda_runtime.h>
#include <cstdint>

#define NU 400000
#define NN 600000
#define MAXNNZ 1200000
#define DV 16              // float4 words per row (D=64)
#define BATCH 8192
#define SEC (BATCH * DV)

#define SCAN_TPB 256
#define SCAN_ITEMS 4
#define SCAN_CHUNK 1024
#define NB_SCAN ((NN + SCAN_CHUNK - 1) / SCAN_CHUNK)   // 586

// ---- scratch (device globals; allocation is forbidden) ----
__device__ float g_bufA[(size_t)NN * 64];
__device__ float g_bufB[(size_t)NN * 64];
__device__ int   g_scol[MAXNNZ];
__device__ float g_sval[MAXNNZ];
__device__ int   g_rowptr[NN];
__device__ int   g_bsums[NB_SCAN];
__device__ int   g_lists[3 * NN];          // levels 1..3 (level l at (l-1)*NN)
// single-memset blob: [0,NN)=deg  [NN,2NN)=wpos  [2NN,3NN)=flags(uint)  [3NN,3NN+4)=cnt
__device__ int   g_blob[3 * NN + 4];

// ================= CSR build =================
__global__ void hist_k(const int* __restrict__ rows, int* __restrict__ deg, int nnz) {
    int e = blockIdx.x * blockDim.x + threadIdx.x;
    if (e < nnz) atomicAdd(&deg[rows[e]], 1);
}

__global__ void scan1_k(const int* __restrict__ deg, int* __restrict__ out,
                        int* __restrict__ bsums) {
    __shared__ int sh[SCAN_TPB];
    int base = blockIdx.x * SCAN_CHUNK + threadIdx.x * SCAN_ITEMS;
    int v[SCAN_ITEMS]; int s = 0;
#pragma unroll
    for (int k = 0; k < SCAN_ITEMS; k++) {
        int idx = base + k;
        v[k] = (idx < NN) ? deg[idx] : 0;
        s += v[k];
    }
    sh[threadIdx.x] = s; __syncthreads();
    for (int off = 1; off < SCAN_TPB; off <<= 1) {
        int t = (threadIdx.x >= off) ? sh[threadIdx.x - off] : 0;
        __syncthreads();
        sh[threadIdx.x] += t;
        __syncthreads();
    }
    int excl = sh[threadIdx.x] - s;
    if (threadIdx.x == SCAN_TPB - 1) bsums[blockIdx.x] = sh[SCAN_TPB - 1];
    int run = excl;
#pragma unroll
    for (int k = 0; k < SCAN_ITEMS; k++) {
        int idx = base + k;
        if (idx < NN) out[idx] = run;
        run += v[k];
    }
}

__global__ void scan2_k(int* __restrict__ bsums) {
    __shared__ int sh[1024];
    int v = (threadIdx.x < NB_SCAN) ? bsums[threadIdx.x] : 0;
    sh[threadIdx.x] = v; __syncthreads();
    for (int off = 1; off < 1024; off <<= 1) {
        int t = (threadIdx.x >= off) ? sh[threadIdx.x - off] : 0;
        __syncthreads();
        sh[threadIdx.x] += t;
        __syncthreads();
    }
    if (threadIdx.x < NB_SCAN) bsums[threadIdx.x] = sh[threadIdx.x] - v;  // exclusive
}

__global__ void scatter_k(const int* __restrict__ rows, const int* __restrict__ cols,
                          const float* __restrict__ vals,
                          const int* __restrict__ rowptr, const int* __restrict__ bsums,
                          int* __restrict__ wpos,
                          int* __restrict__ scol, float* __restrict__ sval, int nnz) {
    int e = blockIdx.x * blockDim.x + threadIdx.x;
    if (e >= nnz) return;
    int r = rows[e];
    int p = rowptr[r] + __ldg(bsums + (r >> 10)) + atomicAdd(&wpos[r], 1);
    scol[p] = cols[e];
    sval[p] = vals[e];
}

// ============ seed flags + init output (acc sections = masked source; ego = same) ============
__global__ void seed_init_k(const float4* __restrict__ ue, const float4* __restrict__ ie,
                            const int4* __restrict__ um, const int4* __restrict__ im,
                            const int* __restrict__ users, const int* __restrict__ pos,
                            const int* __restrict__ neg,
                            unsigned int* __restrict__ flags, float4* __restrict__ out) {
    int i = blockIdx.x * blockDim.x + threadIdx.x;
    if (i >= 3 * SEC) return;
    int sec = i / SEC;
    int rem = i - sec * SEC;
    int b = rem >> 4, lane = rem & 15;
    int row = (sec == 0) ? users[b] : (sec == 1 ? NU + pos[b] : NU + neg[b]);
    float4 e; int4 m;
    if (row < NU) { e = ue[row * DV + lane]; m = um[row * DV + lane]; }
    else          { int j = (row - NU) * DV + lane; e = ie[j]; m = im[j]; }
    float4 v;
    v.x = m.x ? e.x : 0.f;
    v.y = m.y ? e.y : 0.f;
    v.z = m.z ? e.z : 0.f;
    v.w = m.w ? e.w : 0.f;
    out[i] = v;
    out[3 * SEC + i] = v;
    if (lane == 0) flags[row] = 0x01010100u;   // bytes 1,2,3 = levels 1,2,3
}

// ============ frontier pass: fout level byte of col |= fin level byte of row ============
__global__ void fpass_k(const int4* __restrict__ r4, const int4* __restrict__ c4,
                        unsigned char* __restrict__ fb, int inl, int outl,
                        int n4, const int* __restrict__ r, const int* __restrict__ c,
                        int nnz) {
    int i = blockIdx.x * blockDim.x + threadIdx.x;
    if (i < n4) {
        int4 rr = __ldg(r4 + i);
        bool a = fb[rr.x * 4 + inl];
        bool b = fb[rr.y * 4 + inl];
        bool d = fb[rr.z * 4 + inl];
        bool e = fb[rr.w * 4 + inl];
        if (a | b | d | e) {
            int4 cc = __ldg(c4 + i);
            if (a) fb[cc.x * 4 + outl] = 1;
            if (b) fb[cc.y * 4 + outl] = 1;
            if (d) fb[cc.z * 4 + outl] = 1;
            if (e) fb[cc.w * 4 + outl] = 1;
        }
    } else if (i == n4) {
        for (int j = n4 * 4; j < nnz; j++)
            if (fb[r[j] * 4 + inl]) fb[c[j] * 4 + outl] = 1;
    }
}

// ============ compact all 3 levels in one pass (warp-aggregated) ============
__global__ void compact_k(const unsigned int* __restrict__ flags,
                          int* __restrict__ lists, int* __restrict__ cnt) {
    int rr = blockIdx.x * blockDim.x + threadIdx.x;
    unsigned int f = (rr < NN) ? flags[rr] : 0u;
    int lane = threadIdx.x & 31;
#pragma unroll
    for (int l = 1; l <= 3; l++) {
        bool p = (f >> (8 * l)) & 1u;
        unsigned int m = __ballot_sync(0xffffffffu, p);
        if (m) {
            int leader = __ffs(m) - 1;
            int base = 0;
            if (lane == leader) base = atomicAdd(cnt + l, __popc(m));
            base = __shfl_sync(0xffffffffu, base, leader);
            if (p) lists[(l - 1) * NN + base + __popc(m & ((1u << lane) - 1u))] = rr;
        }
    }
}

// ============ layer-1 SpMM with on-the-fly masked x0 gather ============
__global__ void spmm_fused_k(const int* __restrict__ list, const int* __restrict__ cntp,
                             const int* __restrict__ rowptr, const int* __restrict__ bsums,
                             const int* __restrict__ deg,
                             const int* __restrict__ scol, const float* __restrict__ sval,
                             const float4* __restrict__ ue, const float4* __restrict__ ie,
                             const int4* __restrict__ um, const int4* __restrict__ im,
                             float4* __restrict__ y) {
    int n16 = *cntp * DV;
    for (int t = blockIdx.x * blockDim.x + threadIdx.x; t < n16;
         t += gridDim.x * blockDim.x) {
        int r = list[t >> 4];
        int lane = t & 15;
        int s = rowptr[r] + __ldg(bsums + (r >> 10));
        int e = s + deg[r];
        float4 acc = make_float4(0.f, 0.f, 0.f, 0.f);
        for (int j = s; j < e; j++) {
            int c = __ldg(scol + j);
            float v = __ldg(sval + j);
            float4 x; int4 m;
            if (c < NU) { x = __ldg(ue + c * DV + lane); m = __ldg(um + c * DV + lane); }
            else        { int idx = (c - NU) * DV + lane; x = __ldg(ie + idx); m = __ldg(im + idx); }
            if (m.x) acc.x += v * x.x;
            if (m.y) acc.y += v * x.y;
            if (m.z) acc.z += v * x.z;
            if (m.w) acc.w += v * x.w;
        }
        y[(size_t)r * DV + lane] = acc;
    }
}

// ============ layers 2/3: plain CSR SpMM over compacted row list ============
__global__ void spmm_k(const int* __restrict__ list, const int* __restrict__ cntp,
                       const int* __restrict__ rowptr, const int* __restrict__ bsums,
                       const int* __restrict__ deg,
                       const int* __restrict__ scol, const float* __restrict__ sval,
                       const float4* __restrict__ x, float4* __restrict__ y) {
    int n16 = *cntp * DV;
    for (int t = blockIdx.x * blockDim.x + threadIdx.x; t < n16;
         t += gridDim.x * blockDim.x) {
        int r = list[t >> 4];
        int lane = t & 15;
        int s = rowptr[r] + __ldg(bsums + (r >> 10));
        int e = s + deg[r];
        float4 acc = make_float4(0.f, 0.f, 0.f, 0.f);
        for (int j = s; j < e; j++) {
            int c = __ldg(scol + j);
            float v = __ldg(sval + j);
            float4 xv = __ldg(x + (size_t)c * DV + lane);
            acc.x += v * xv.x;
            acc.y += v * xv.y;
            acc.z += v * xv.z;
            acc.w += v * xv.w;
        }
        y[(size_t)r * DV + lane] = acc;
    }
}

// ============ accumulate layer into output batch sections ============
__global__ void acc_k(const float4* __restrict__ buf,
                      const int* __restrict__ users, const int* __restrict__ pos,
                      const int* __restrict__ neg, float4* __restrict__ out, float scale) {
    int i = blockIdx.x * blockDim.x + threadIdx.x;
    if (i >= 3 * SEC) return;
    int sec = i / SEC;
    int rem = i - sec * SEC;
    int b = rem >> 4;
    int row = (sec == 0) ? users[b] : (sec == 1 ? NU + pos[b] : NU + neg[b]);
    float4 v = buf[(size_t)row * DV + (rem & 15)];
    float4 o = out[i];
    o.x = (o.x + v.x) * scale;
    o.y = (o.y + v.y) * scale;
    o.z = (o.z + v.z) * scale;
    o.w = (o.w + v.w) * scale;
    out[i] = o;
}

extern "C" void kernel_launch(void* const* d_in, const int* in_sizes, int n_in,
                              void* d_out, int out_size) {
    const float* ue   = (const float*)d_in[0];
    const float* ie   = (const float*)d_in[1];
    const int*   um   = (const int*)  d_in[2];
    const int*   im   = (const int*)  d_in[3];
    const int*   rows = (const int*)  d_in[4];
    const int*   cols = (const int*)  d_in[5];
    const float* vals = (const float*)d_in[6];
    const int*   users= (const int*)  d_in[7];
    const int*   pos  = (const int*)  d_in[8];
    const int*   neg  = (const int*)  d_in[9];
    int nnz = in_sizes[4];
    float* out = (float*)d_out;

    float *bufA, *bufB, *sval;
    int *scol, *rowptr, *bsums, *lists, *blob;
    cudaGetSymbolAddress((void**)&bufA, g_bufA);
    cudaGetSymbolAddress((void**)&bufB, g_bufB);
    cudaGetSymbolAddress((void**)&scol, g_scol);
    cudaGetSymbolAddress((void**)&sval, g_sval);
    cudaGetSymbolAddress((void**)&rowptr, g_rowptr);
    cudaGetSymbolAddress((void**)&bsums, g_bsums);
    cudaGetSymbolAddress((void**)&lists, g_lists);
    cudaGetSymbolAddress((void**)&blob, g_blob);

    int* deg  = blob;
    int* wpos = blob + NN;
    unsigned int* flags = (unsigned int*)(blob + 2 * NN);
    int* cnt  = blob + 3 * NN;

    const int TPB = 256;
    const int eBlocks = (nnz + TPB - 1) / TPB;
    const int nBlocks = (NN + TPB - 1) / TPB;
    const int gBlocks = (3 * SEC + TPB - 1) / TPB;
    const int n4 = nnz / 4;
    const int fBlocks = (n4 + 1 + TPB - 1) / TPB;
    const int GS = 4096;

    // one memset clears deg, wpos, flags, cnt
    cudaMemsetAsync(blob, 0, (3 * NN + 4) * sizeof(int));

    // CSR build
    hist_k<<<eBlocks, TPB>>>(rows, deg, nnz);
    scan1_k<<<NB_SCAN, SCAN_TPB>>>(deg, rowptr, bsums);
    scan2_k<<<1, 1024>>>(bsums);
    scatter_k<<<eBlocks, TPB>>>(rows, cols, vals, rowptr, bsums, wpos, scol, sval, nnz);

    // seed flags + init output, then 2 frontier hops + single compaction
    seed_init_k<<<gBlocks, TPB>>>((const float4*)ue, (const float4*)ie,
                                  (const int4*)um, (const int4*)im,
                                  users, pos, neg, flags, (float4*)out);
    unsigned char* fb = (unsigned char*)flags;
    fpass_k<<<fBlocks, TPB>>>((const int4*)rows, (const int4*)cols, fb, 3, 2,
                              n4, rows, cols, nnz);
    fpass_k<<<fBlocks, TPB>>>((const int4*)rows, (const int4*)cols, fb, 2, 1,
                              n4, rows, cols, nnz);
    compact_k<<<nBlocks, TPB>>>(flags, lists, cnt);

    // layer 1: fused masked gather, x0 never materialized
    spmm_fused_k<<<GS, TPB>>>(lists + 0 * NN, cnt + 1, rowptr, bsums, deg, scol, sval,
                              (const float4*)ue, (const float4*)ie,
                              (const int4*)um, (const int4*)im, (float4*)bufB);
    acc_k<<<gBlocks, TPB>>>((const float4*)bufB, users, pos, neg, (float4*)out, 1.0f);

    // layer 2
    spmm_k<<<GS, TPB>>>(lists + 1 * NN, cnt + 2, rowptr, bsums, deg, scol, sval,
                        (const float4*)bufB, (float4*)bufA);
    acc_k<<<gBlocks, TPB>>>((const float4*)bufA, users, pos, neg, (float4*)out, 1.0f);

    // layer 3
    spmm_k<<<GS, TPB>>>(lists + 2 * NN, cnt + 3, rowptr, bsums, deg, scol, sval,
                        (const float4*)bufA, (float4*)bufB);
    acc_k<<<gBlocks, TPB>>>((const float4*)bufB, users, pos, neg, (float4*)out, 0.25f);
}

// round 5
// speedup vs baseline: 2.3447x; 1.0732x over previous
#include <cuda_runtime.h>
#include <cstdint>

#define NU 400000
#define NN 600000
#define MAXNNZ 1200000
#define DV 16              // float4 words per row (D=64)
#define BATCH 8192
#define SEC (BATCH * DV)

#define SCAN_TPB 256
#define SCAN_ITEMS 4
#define SCAN_CHUNK 1024
#define NB_SCAN ((NN + SCAN_CHUNK - 1) / SCAN_CHUNK)   // 586

// ---- scratch (device globals; allocation is forbidden) ----
__device__ float g_bufA[(size_t)NN * 64];
__device__ float g_bufB[(size_t)NN * 64];
__device__ float g_bufC[(size_t)NN * 64];
__device__ int   g_scol[MAXNNZ];
__device__ float g_sval[MAXNNZ];
__device__ int   g_rowptr[NN];
__device__ int   g_bsums[NB_SCAN];
__device__ int   g_lists[3 * NN];          // levels 1..3 (level l at (l-1)*NN)
// single-memset blob: [0,NN)=deg  [NN,2NN)=wpos  [2NN,3NN)=flags(uint)  [3NN,+4)=cnt
__device__ int   g_blob[3 * NN + 4];

// ================= CSR build (ILP-4) =================
__global__ void hist_k(const int4* __restrict__ r4, int* __restrict__ deg,
                       int n4, const int* __restrict__ r, int nnz) {
    int i = blockIdx.x * blockDim.x + threadIdx.x;
    if (i < n4) {
        int4 rr = __ldg(r4 + i);
        atomicAdd(&deg[rr.x], 1);
        atomicAdd(&deg[rr.y], 1);
        atomicAdd(&deg[rr.z], 1);
        atomicAdd(&deg[rr.w], 1);
    } else if (i == n4) {
        for (int j = n4 * 4; j < nnz; j++) atomicAdd(&deg[r[j]], 1);
    }
}

__global__ void scan1_k(const int* __restrict__ deg, int* __restrict__ out,
                        int* __restrict__ bsums) {
    __shared__ int sh[SCAN_TPB];
    int base = blockIdx.x * SCAN_CHUNK + threadIdx.x * SCAN_ITEMS;
    int v[SCAN_ITEMS]; int s = 0;
#pragma unroll
    for (int k = 0; k < SCAN_ITEMS; k++) {
        int idx = base + k;
        v[k] = (idx < NN) ? deg[idx] : 0;
        s += v[k];
    }
    sh[threadIdx.x] = s; __syncthreads();
    for (int off = 1; off < SCAN_TPB; off <<= 1) {
        int t = (threadIdx.x >= off) ? sh[threadIdx.x - off] : 0;
        __syncthreads();
        sh[threadIdx.x] += t;
        __syncthreads();
    }
    int excl = sh[threadIdx.x] - s;
    if (threadIdx.x == SCAN_TPB - 1) bsums[blockIdx.x] = sh[SCAN_TPB - 1];
    int run = excl;
#pragma unroll
    for (int k = 0; k < SCAN_ITEMS; k++) {
        int idx = base + k;
        if (idx < NN) out[idx] = run;
        run += v[k];
    }
}

__global__ void scan2_k(int* __restrict__ bsums) {
    __shared__ int sh[1024];
    int v = (threadIdx.x < NB_SCAN) ? bsums[threadIdx.x] : 0;
    sh[threadIdx.x] = v; __syncthreads();
    for (int off = 1; off < 1024; off <<= 1) {
        int t = (threadIdx.x >= off) ? sh[threadIdx.x - off] : 0;
        __syncthreads();
        sh[threadIdx.x] += t;
        __syncthreads();
    }
    if (threadIdx.x < NB_SCAN) bsums[threadIdx.x] = sh[threadIdx.x] - v;  // exclusive
}

__device__ __forceinline__ int csr_base(const int* rowptr, const int* bsums, int r) {
    return rowptr[r] + __ldg(bsums + (r >> 10));
}

__global__ void scatter_k(const int4* __restrict__ r4, const int4* __restrict__ c4,
                          const float4* __restrict__ v4,
                          const int* __restrict__ rowptr, const int* __restrict__ bsums,
                          int* __restrict__ wpos,
                          int* __restrict__ scol, float* __restrict__ sval,
                          int n4, const int* __restrict__ r, const int* __restrict__ c,
                          const float* __restrict__ v, int nnz) {
    int i = blockIdx.x * blockDim.x + threadIdx.x;
    if (i < n4) {
        int4 rr = __ldg(r4 + i);
        int4 cc = __ldg(c4 + i);
        float4 vv = __ldg(v4 + i);
        int p0 = csr_base(rowptr, bsums, rr.x) + atomicAdd(&wpos[rr.x], 1);
        int p1 = csr_base(rowptr, bsums, rr.y) + atomicAdd(&wpos[rr.y], 1);
        int p2 = csr_base(rowptr, bsums, rr.z) + atomicAdd(&wpos[rr.z], 1);
        int p3 = csr_base(rowptr, bsums, rr.w) + atomicAdd(&wpos[rr.w], 1);
        scol[p0] = cc.x; sval[p0] = vv.x;
        scol[p1] = cc.y; sval[p1] = vv.y;
        scol[p2] = cc.z; sval[p2] = vv.z;
        scol[p3] = cc.w; sval[p3] = vv.w;
    } else if (i == n4) {
        for (int j = n4 * 4; j < nnz; j++) {
            int rj = r[j];
            int p = csr_base(rowptr, bsums, rj) + atomicAdd(&wpos[rj], 1);
            scol[p] = c[j]; sval[p] = v[j];
        }
    }
}

// ============ seed flags + init output (acc sections = masked source; ego = same) ============
__global__ void seed_init_k(const float4* __restrict__ ue, const float4* __restrict__ ie,
                            const int4* __restrict__ um, const int4* __restrict__ im,
                            const int* __restrict__ users, const int* __restrict__ pos,
                            const int* __restrict__ neg,
                            unsigned int* __restrict__ flags, float4* __restrict__ out) {
    int i = blockIdx.x * blockDim.x + threadIdx.x;
    if (i >= 3 * SEC) return;
    int sec = i / SEC;
    int rem = i - sec * SEC;
    int b = rem >> 4, lane = rem & 15;
    int row = (sec == 0) ? users[b] : (sec == 1 ? NU + pos[b] : NU + neg[b]);
    float4 e; int4 m;
    if (row < NU) { e = ue[row * DV + lane]; m = um[row * DV + lane]; }
    else          { int j = (row - NU) * DV + lane; e = ie[j]; m = im[j]; }
    float4 v;
    v.x = m.x ? e.x : 0.f;
    v.y = m.y ? e.y : 0.f;
    v.z = m.z ? e.z : 0.f;
    v.w = m.w ? e.w : 0.f;
    out[i] = v;
    out[3 * SEC + i] = v;
    if (lane == 0) flags[row] = 0x01010100u;   // bytes 1,2,3 = levels 1,2,3
}

// ============ frontier pass (ILP-8): col's outl byte |= row's inl byte ============
__global__ void fpass_k(const int4* __restrict__ r4, const int4* __restrict__ c4,
                        unsigned char* __restrict__ fb, int inl, int outl,
                        int n8, const int* __restrict__ r, const int* __restrict__ c,
                        int nnz) {
    int i = blockIdx.x * blockDim.x + threadIdx.x;
    if (i < n8) {
        int4 ra = __ldg(r4 + 2 * i), rb = __ldg(r4 + 2 * i + 1);
        bool a0 = fb[ra.x * 4 + inl], a1 = fb[ra.y * 4 + inl];
        bool a2 = fb[ra.z * 4 + inl], a3 = fb[ra.w * 4 + inl];
        bool b0 = fb[rb.x * 4 + inl], b1 = fb[rb.y * 4 + inl];
        bool b2 = fb[rb.z * 4 + inl], b3 = fb[rb.w * 4 + inl];
        if (a0 | a1 | a2 | a3) {
            int4 ca = __ldg(c4 + 2 * i);
            if (a0) fb[ca.x * 4 + outl] = 1;
            if (a1) fb[ca.y * 4 + outl] = 1;
            if (a2) fb[ca.z * 4 + outl] = 1;
            if (a3) fb[ca.w * 4 + outl] = 1;
        }
        if (b0 | b1 | b2 | b3) {
            int4 cb = __ldg(c4 + 2 * i + 1);
            if (b0) fb[cb.x * 4 + outl] = 1;
            if (b1) fb[cb.y * 4 + outl] = 1;
            if (b2) fb[cb.z * 4 + outl] = 1;
            if (b3) fb[cb.w * 4 + outl] = 1;
        }
    } else if (i == n8) {
        for (int j = n8 * 8; j < nnz; j++)
            if (fb[r[j] * 4 + inl]) fb[c[j] * 4 + outl] = 1;
    }
}

// ============ compact all 3 levels in one pass (warp-aggregated) ============
__global__ void compact_k(const unsigned int* __restrict__ flags,
                          int* __restrict__ lists, int* __restrict__ cnt) {
    int rr = blockIdx.x * blockDim.x + threadIdx.x;
    unsigned int f = (rr < NN) ? flags[rr] : 0u;
    int lane = threadIdx.x & 31;
#pragma unroll
    for (int l = 1; l <= 3; l++) {
        bool p = (f >> (8 * l)) & 1u;
        unsigned int m = __ballot_sync(0xffffffffu, p);
        if (m) {
            int leader = __ffs(m) - 1;
            int base = 0;
            if (lane == leader) base = atomicAdd(cnt + l, __popc(m));
            base = __shfl_sync(0xffffffffu, base, leader);
            if (p) lists[(l - 1) * NN + base + __popc(m & ((1u << lane) - 1u))] = rr;
        }
    }
}

// ============ layer-1 SpMM with on-the-fly masked x0 gather ============
__global__ void spmm_fused_k(const int* __restrict__ list, const int* __restrict__ cntp,
                             const int* __restrict__ rowptr, const int* __restrict__ bsums,
                             const int* __restrict__ deg,
                             const int* __restrict__ scol, const float* __restrict__ sval,
                             const float4* __restrict__ ue, const float4* __restrict__ ie,
                             const int4* __restrict__ um, const int4* __restrict__ im,
                             float4* __restrict__ y) {
    int n16 = *cntp * DV;
    for (int t = blockIdx.x * blockDim.x + threadIdx.x; t < n16;
         t += gridDim.x * blockDim.x) {
        int r = list[t >> 4];
        int lane = t & 15;
        int s = rowptr[r] + __ldg(bsums + (r >> 10));
        int e = s + deg[r];
        float4 acc = make_float4(0.f, 0.f, 0.f, 0.f);
        for (int j = s; j < e; j++) {
            int c = __ldg(scol + j);
            float v = __ldg(sval + j);
            float4 x; int4 m;
            if (c < NU) { x = __ldg(ue + c * DV + lane); m = __ldg(um + c * DV + lane); }
            else        { int idx = (c - NU) * DV + lane; x = __ldg(ie + idx); m = __ldg(im + idx); }
            if (m.x) acc.x += v * x.x;
            if (m.y) acc.y += v * x.y;
            if (m.z) acc.z += v * x.z;
            if (m.w) acc.w += v * x.w;
        }
        y[(size_t)r * DV + lane] = acc;
    }
}

// ============ layers 2/3: plain CSR SpMM over compacted row list ============
__global__ void spmm_k(const int* __restrict__ list, const int* __restrict__ cntp,
                       const int* __restrict__ rowptr, const int* __restrict__ bsums,
                       const int* __restrict__ deg,
                       const int* __restrict__ scol, const float* __restrict__ sval,
                       const float4* __restrict__ x, float4* __restrict__ y) {
    int n16 = *cntp * DV;
    for (int t = blockIdx.x * blockDim.x + threadIdx.x; t < n16;
         t += gridDim.x * blockDim.x) {
        int r = list[t >> 4];
        int lane = t & 15;
        int s = rowptr[r] + __ldg(bsums + (r >> 10));
        int e = s + deg[r];
        float4 acc = make_float4(0.f, 0.f, 0.f, 0.f);
        for (int j = s; j < e; j++) {
            int c = __ldg(scol + j);
            float v = __ldg(sval + j);
            float4 xv = __ldg(x + (size_t)c * DV + lane);
            acc.x += v * xv.x;
            acc.y += v * xv.y;
            acc.z += v * xv.z;
            acc.w += v * xv.w;
        }
        y[(size_t)r * DV + lane] = acc;
    }
}

// ============ single deferred accumulate: out = (init + l1 + l2 + l3) / 4 ============
__global__ void final_acc_k(const float4* __restrict__ l1, const float4* __restrict__ l2,
                            const float4* __restrict__ l3,
                            const int* __restrict__ users, const int* __restrict__ pos,
                            const int* __restrict__ neg, float4* __restrict__ out) {
    int i = blockIdx.x * blockDim.x + threadIdx.x;
    if (i >= 3 * SEC) return;
    int sec = i / SEC;
    int rem = i - sec * SEC;
    int b = rem >> 4;
    int row = (sec == 0) ? users[b] : (sec == 1 ? NU + pos[b] : NU + neg[b]);
    size_t o = (size_t)row * DV + (rem & 15);
    float4 a = out[i], v1 = l1[o], v2 = l2[o], v3 = l3[o];
    float4 r;
    r.x = (a.x + v1.x + v2.x + v3.x) * 0.25f;
    r.y = (a.y + v1.y + v2.y + v3.y) * 0.25f;
    r.z = (a.z + v1.z + v2.z + v3.z) * 0.25f;
    r.w = (a.w + v1.w + v2.w + v3.w) * 0.25f;
    out[i] = r;
}

extern "C" void kernel_launch(void* const* d_in, const int* in_sizes, int n_in,
                              void* d_out, int out_size) {
    const float* ue   = (const float*)d_in[0];
    const float* ie   = (const float*)d_in[1];
    const int*   um   = (const int*)  d_in[2];
    const int*   im   = (const int*)  d_in[3];
    const int*   rows = (const int*)  d_in[4];
    const int*   cols = (const int*)  d_in[5];
    const float* vals = (const float*)d_in[6];
    const int*   users= (const int*)  d_in[7];
    const int*   pos  = (const int*)  d_in[8];
    const int*   neg  = (const int*)  d_in[9];
    int nnz = in_sizes[4];
    float* out = (float*)d_out;

    float *bufA, *bufB, *bufC, *sval;
    int *scol, *rowptr, *bsums, *lists, *blob;
    cudaGetSymbolAddress((void**)&bufA, g_bufA);
    cudaGetSymbolAddress((void**)&bufB, g_bufB);
    cudaGetSymbolAddress((void**)&bufC, g_bufC);
    cudaGetSymbolAddress((void**)&scol, g_scol);
    cudaGetSymbolAddress((void**)&sval, g_sval);
    cudaGetSymbolAddress((void**)&rowptr, g_rowptr);
    cudaGetSymbolAddress((void**)&bsums, g_bsums);
    cudaGetSymbolAddress((void**)&lists, g_lists);
    cudaGetSymbolAddress((void**)&blob, g_blob);

    int* deg  = blob;
    int* wpos = blob + NN;
    unsigned int* flags = (unsigned int*)(blob + 2 * NN);
    int* cnt  = blob + 3 * NN;

    // lazily-created aux stream + fork/join events (host-side handles only)
    static cudaStream_t sAux = nullptr;
    static cudaEvent_t evFork = nullptr, evJoin = nullptr;
    if (sAux == nullptr) {
        cudaStreamCreateWithFlags(&sAux, cudaStreamNonBlocking);
        cudaEventCreateWithFlags(&evFork, cudaEventDisableTiming);
        cudaEventCreateWithFlags(&evJoin, cudaEventDisableTiming);
    }

    const int TPB = 256;
    const int nBlocks = (NN + TPB - 1) / TPB;
    const int gBlocks = (3 * SEC + TPB - 1) / TPB;
    const int n4 = nnz / 4;
    const int n8 = nnz / 8;
    const int e4Blocks = (n4 + 1 + TPB - 1) / TPB;
    const int e8Blocks = (n8 + 1 + TPB - 1) / TPB;
    const int GS = 4096;

    // one memset clears deg, wpos, flags, cnt
    cudaMemsetAsync(blob, 0, (3 * NN + 4) * sizeof(int));
    cudaEventRecord(evFork, 0);
    cudaStreamWaitEvent(sAux, evFork, 0);

    // ---- chain A (default stream): CSR build ----
    hist_k<<<e4Blocks, TPB>>>((const int4*)rows, deg, n4, rows, nnz);
    scan1_k<<<NB_SCAN, SCAN_TPB>>>(deg, rowptr, bsums);
    scan2_k<<<1, 1024>>>(bsums);
    scatter_k<<<e4Blocks, TPB>>>((const int4*)rows, (const int4*)cols, (const float4*)vals,
                                 rowptr, bsums, wpos, scol, sval,
                                 n4, rows, cols, vals, nnz);

    // ---- chain B (aux stream): seed + frontiers + compaction ----
    unsigned char* fb = (unsigned char*)flags;
    seed_init_k<<<gBlocks, TPB, 0, sAux>>>((const float4*)ue, (const float4*)ie,
                                           (const int4*)um, (const int4*)im,
                                           users, pos, neg, flags, (float4*)out);
    fpass_k<<<e8Blocks, TPB, 0, sAux>>>((const int4*)rows, (const int4*)cols, fb, 3, 2,
                                        n8, rows, cols, nnz);
    fpass_k<<<e8Blocks, TPB, 0, sAux>>>((const int4*)rows, (const int4*)cols, fb, 2, 1,
                                        n8, rows, cols, nnz);
    compact_k<<<nBlocks, TPB, 0, sAux>>>(flags, lists, cnt);
    cudaEventRecord(evJoin, sAux);
    cudaStreamWaitEvent(0, evJoin, 0);

    // ---- 3 SpMM layers (distinct dst buffers), then one deferred accumulate ----
    spmm_fused_k<<<GS, TPB>>>(lists + 0 * NN, cnt + 1, rowptr, bsums, deg, scol, sval,
                              (const float4*)ue, (const float4*)ie,
                              (const int4*)um, (const int4*)im, (float4*)bufA);
    spmm_k<<<GS, TPB>>>(lists + 1 * NN, cnt + 2, rowptr, bsums, deg, scol, sval,
                        (const float4*)bufA, (float4*)bufB);
    spmm_k<<<GS, TPB>>>(lists + 2 * NN, cnt + 3, rowptr, bsums, deg, scol, sval,
                        (const float4*)bufB, (float4*)bufC);
    final_acc_k<<<gBlocks, TPB>>>((const float4*)bufA, (const float4*)bufB,
                                  (const float4*)bufC, users, pos, neg, (float4*)out);
}

// round 6
// speedup vs baseline: 2.4833x; 1.0591x over previous
#include <cuda_runtime.h>
#include <cstdint>

#define NU 400000
#define NN 600000
#define MAXNNZ 1200000
#define DV 16              // float4 words per row (D=64)
#define BATCH 8192
#define SEC (BATCH * DV)

#define SCAN_TPB 256
#define SCAN_ITEMS 4
#define SCAN_CHUNK 1024
#define NB_SCAN ((NN + SCAN_CHUNK - 1) / SCAN_CHUNK)   // 586

// ---- scratch (device globals; allocation is forbidden) ----
__device__ float g_bufA[(size_t)NN * 64];
__device__ float g_bufB[(size_t)NN * 64];
__device__ float g_bufC[(size_t)NN * 64];
__device__ int2  g_scsr[MAXNNZ];           // packed {col, val}
__device__ int   g_rowptr[NN];
__device__ int   g_bsums[NB_SCAN];
__device__ int   g_lists[3 * NN];          // levels 1..3 (level l at (l-1)*NN)
// single-memset blob: [0,NN)=deg  [NN,2NN)=wpos  [2NN,3NN)=flags(uint)  [3NN,+4)=cnt
__device__ int   g_blob[3 * NN + 4];

// ================= CSR build (symmetric half-edge, ILP-4) =================
// Processes undirected pairs: edge e in [0,E) covers directed edges e and E+e.
__global__ void hist_k(const int4* __restrict__ r4, const int4* __restrict__ c4,
                       int* __restrict__ deg,
                       int n4, const int* __restrict__ r, const int* __restrict__ c, int E) {
    int i = blockIdx.x * blockDim.x + threadIdx.x;
    if (i < n4) {
        int4 rr = __ldg(r4 + i);
        int4 cc = __ldg(c4 + i);
        atomicAdd(&deg[rr.x], 1); atomicAdd(&deg[cc.x], 1);
        atomicAdd(&deg[rr.y], 1); atomicAdd(&deg[cc.y], 1);
        atomicAdd(&deg[rr.z], 1); atomicAdd(&deg[cc.z], 1);
        atomicAdd(&deg[rr.w], 1); atomicAdd(&deg[cc.w], 1);
    } else if (i == n4) {
        for (int j = n4 * 4; j < E; j++) { atomicAdd(&deg[r[j]], 1); atomicAdd(&deg[c[j]], 1); }
    }
}

__global__ void scan1_k(const int* __restrict__ deg, int* __restrict__ out,
                        int* __restrict__ bsums) {
    __shared__ int sh[SCAN_TPB];
    int base = blockIdx.x * SCAN_CHUNK + threadIdx.x * SCAN_ITEMS;
    int v[SCAN_ITEMS]; int s = 0;
#pragma unroll
    for (int k = 0; k < SCAN_ITEMS; k++) {
        int idx = base + k;
        v[k] = (idx < NN) ? deg[idx] : 0;
        s += v[k];
    }
    sh[threadIdx.x] = s; __syncthreads();
    for (int off = 1; off < SCAN_TPB; off <<= 1) {
        int t = (threadIdx.x >= off) ? sh[threadIdx.x - off] : 0;
        __syncthreads();
        sh[threadIdx.x] += t;
        __syncthreads();
    }
    int excl = sh[threadIdx.x] - s;
    if (threadIdx.x == SCAN_TPB - 1) bsums[blockIdx.x] = sh[SCAN_TPB - 1];
    int run = excl;
#pragma unroll
    for (int k = 0; k < SCAN_ITEMS; k++) {
        int idx = base + k;
        if (idx < NN) out[idx] = run;
        run += v[k];
    }
}

__global__ void scan2_k(int* __restrict__ bsums) {
    __shared__ int sh[1024];
    int v = (threadIdx.x < NB_SCAN) ? bsums[threadIdx.x] : 0;
    sh[threadIdx.x] = v; __syncthreads();
    for (int off = 1; off < 1024; off <<= 1) {
        int t = (threadIdx.x >= off) ? sh[threadIdx.x - off] : 0;
        __syncthreads();
        sh[threadIdx.x] += t;
        __syncthreads();
    }
    if (threadIdx.x < NB_SCAN) bsums[threadIdx.x] = sh[threadIdx.x] - v;  // exclusive
}

__device__ __forceinline__ int csr_base(const int* rowptr, const int* bsums, int r) {
    return rowptr[r] + __ldg(bsums + (r >> 10));
}

// Symmetric scatter: edge (u,it,v) inserts {it,v} in row u and {u,v} in row it.
__global__ void scatter_k(const int4* __restrict__ r4, const int4* __restrict__ c4,
                          const float4* __restrict__ v4,
                          const int* __restrict__ rowptr, const int* __restrict__ bsums,
                          int* __restrict__ wpos, int2* __restrict__ csr,
                          int n4, const int* __restrict__ r, const int* __restrict__ c,
                          const float* __restrict__ v, int E) {
    int i = blockIdx.x * blockDim.x + threadIdx.x;
    if (i < n4) {
        int4 rr = __ldg(r4 + i);
        int4 cc = __ldg(c4 + i);
        float4 vv = __ldg(v4 + i);
        int pr0 = csr_base(rowptr, bsums, rr.x) + atomicAdd(&wpos[rr.x], 1);
        int pc0 = csr_base(rowptr, bsums, cc.x) + atomicAdd(&wpos[cc.x], 1);
        int pr1 = csr_base(rowptr, bsums, rr.y) + atomicAdd(&wpos[rr.y], 1);
        int pc1 = csr_base(rowptr, bsums, cc.y) + atomicAdd(&wpos[cc.y], 1);
        int pr2 = csr_base(rowptr, bsums, rr.z) + atomicAdd(&wpos[rr.z], 1);
        int pc2 = csr_base(rowptr, bsums, cc.z) + atomicAdd(&wpos[cc.z], 1);
        int pr3 = csr_base(rowptr, bsums, rr.w) + atomicAdd(&wpos[rr.w], 1);
        int pc3 = csr_base(rowptr, bsums, cc.w) + atomicAdd(&wpos[cc.w], 1);
        csr[pr0] = make_int2(cc.x, __float_as_int(vv.x));
        csr[pc0] = make_int2(rr.x, __float_as_int(vv.x));
        csr[pr1] = make_int2(cc.y, __float_as_int(vv.y));
        csr[pc1] = make_int2(rr.y, __float_as_int(vv.y));
        csr[pr2] = make_int2(cc.z, __float_as_int(vv.z));
        csr[pc2] = make_int2(rr.z, __float_as_int(vv.z));
        csr[pr3] = make_int2(cc.w, __float_as_int(vv.w));
        csr[pc3] = make_int2(rr.w, __float_as_int(vv.w));
    } else if (i == n4) {
        for (int j = n4 * 4; j < E; j++) {
            int rj = r[j], cj = c[j]; float vj = v[j];
            int pr = csr_base(rowptr, bsums, rj) + atomicAdd(&wpos[rj], 1);
            int pc = csr_base(rowptr, bsums, cj) + atomicAdd(&wpos[cj], 1);
            csr[pr] = make_int2(cj, __float_as_int(vj));
            csr[pc] = make_int2(rj, __float_as_int(vj));
        }
    }
}

// ============ seed flags + init output (acc sections = masked source; ego = same) ============
__global__ void seed_init_k(const float4* __restrict__ ue, const float4* __restrict__ ie,
                            const int4* __restrict__ um, const int4* __restrict__ im,
                            const int* __restrict__ users, const int* __restrict__ pos,
                            const int* __restrict__ neg,
                            unsigned int* __restrict__ flags, float4* __restrict__ out) {
    int i = blockIdx.x * blockDim.x + threadIdx.x;
    if (i >= 3 * SEC) return;
    int sec = i / SEC;
    int rem = i - sec * SEC;
    int b = rem >> 4, lane = rem & 15;
    int row = (sec == 0) ? users[b] : (sec == 1 ? NU + pos[b] : NU + neg[b]);
    float4 e; int4 m;
    if (row < NU) { e = ue[row * DV + lane]; m = um[row * DV + lane]; }
    else          { int j = (row - NU) * DV + lane; e = ie[j]; m = im[j]; }
    float4 v;
    v.x = m.x ? e.x : 0.f;
    v.y = m.y ? e.y : 0.f;
    v.z = m.z ? e.z : 0.f;
    v.w = m.w ? e.w : 0.f;
    out[i] = v;
    out[3 * SEC + i] = v;
    if (lane == 0) flags[row] = 0x01010100u;   // bytes 1,2,3 = levels 1,2,3
}

// ============ frontier pass (symmetric, ILP-4): both directions per undirected edge ============
__global__ void fpass_k(const int4* __restrict__ r4, const int4* __restrict__ c4,
                        unsigned char* __restrict__ fb, int inl, int outl,
                        int n4, const int* __restrict__ r, const int* __restrict__ c, int E) {
    int i = blockIdx.x * blockDim.x + threadIdx.x;
    if (i < n4) {
        int4 rr = __ldg(r4 + i);
        int4 cc = __ldg(c4 + i);
        bool r0 = fb[rr.x * 4 + inl], r1 = fb[rr.y * 4 + inl];
        bool r2 = fb[rr.z * 4 + inl], r3 = fb[rr.w * 4 + inl];
        bool c0 = fb[cc.x * 4 + inl], c1 = fb[cc.y * 4 + inl];
        bool c2 = fb[cc.z * 4 + inl], c3 = fb[cc.w * 4 + inl];
        if (r0) fb[cc.x * 4 + outl] = 1;
        if (r1) fb[cc.y * 4 + outl] = 1;
        if (r2) fb[cc.z * 4 + outl] = 1;
        if (r3) fb[cc.w * 4 + outl] = 1;
        if (c0) fb[rr.x * 4 + outl] = 1;
        if (c1) fb[rr.y * 4 + outl] = 1;
        if (c2) fb[rr.z * 4 + outl] = 1;
        if (c3) fb[rr.w * 4 + outl] = 1;
    } else if (i == n4) {
        for (int j = n4 * 4; j < E; j++) {
            if (fb[r[j] * 4 + inl]) fb[c[j] * 4 + outl] = 1;
            if (fb[c[j] * 4 + inl]) fb[r[j] * 4 + outl] = 1;
        }
    }
}

// ============ compact all 3 levels in one pass (warp-aggregated) ============
__global__ void compact_k(const unsigned int* __restrict__ flags,
                          int* __restrict__ lists, int* __restrict__ cnt) {
    int rr = blockIdx.x * blockDim.x + threadIdx.x;
    unsigned int f = (rr < NN) ? flags[rr] : 0u;
    int lane = threadIdx.x & 31;
#pragma unroll
    for (int l = 1; l <= 3; l++) {
        bool p = (f >> (8 * l)) & 1u;
        unsigned int m = __ballot_sync(0xffffffffu, p);
        if (m) {
            int leader = __ffs(m) - 1;
            int base = 0;
            if (lane == leader) base = atomicAdd(cnt + l, __popc(m));
            base = __shfl_sync(0xffffffffu, base, leader);
            if (p) lists[(l - 1) * NN + base + __popc(m & ((1u << lane) - 1u))] = rr;
        }
    }
}

// ============ layer-1 SpMM with on-the-fly masked x0 gather (pair-unrolled) ============
__global__ void spmm_fused_k(const int* __restrict__ list, const int* __restrict__ cntp,
                             const int* __restrict__ rowptr, const int* __restrict__ bsums,
                             const int* __restrict__ deg, const int2* __restrict__ csr,
                             const float4* __restrict__ ue, const float4* __restrict__ ie,
                             const int4* __restrict__ um, const int4* __restrict__ im,
                             float4* __restrict__ y) {
    int n16 = *cntp * DV;
    for (int t = blockIdx.x * blockDim.x + threadIdx.x; t < n16;
         t += gridDim.x * blockDim.x) {
        int r = list[t >> 4];
        int lane = t & 15;
        int s = rowptr[r] + __ldg(bsums + (r >> 10));
        int e = s + deg[r];
        float4 acc = make_float4(0.f, 0.f, 0.f, 0.f);
        int j = s;
        for (; j + 2 <= e; j += 2) {
            int2 q0 = __ldg(csr + j);
            int2 q1 = __ldg(csr + j + 1);
            float v0 = __int_as_float(q0.y), v1 = __int_as_float(q1.y);
            int i0 = (q0.x < NU) ? q0.x * DV + lane : (q0.x - NU) * DV + lane;
            int i1 = (q1.x < NU) ? q1.x * DV + lane : (q1.x - NU) * DV + lane;
            float4 x0 = (q0.x < NU) ? __ldg(ue + i0) : __ldg(ie + i0);
            float4 x1 = (q1.x < NU) ? __ldg(ue + i1) : __ldg(ie + i1);
            int4 m0 = (q0.x < NU) ? __ldg(um + i0) : __ldg(im + i0);
            int4 m1 = (q1.x < NU) ? __ldg(um + i1) : __ldg(im + i1);
            if (m0.x) acc.x += v0 * x0.x;
            if (m0.y) acc.y += v0 * x0.y;
            if (m0.z) acc.z += v0 * x0.z;
            if (m0.w) acc.w += v0 * x0.w;
            if (m1.x) acc.x += v1 * x1.x;
            if (m1.y) acc.y += v1 * x1.y;
            if (m1.z) acc.z += v1 * x1.z;
            if (m1.w) acc.w += v1 * x1.w;
        }
        if (j < e) {
            int2 q = __ldg(csr + j);
            float v = __int_as_float(q.y);
            int i0 = (q.x < NU) ? q.x * DV + lane : (q.x - NU) * DV + lane;
            float4 x = (q.x < NU) ? __ldg(ue + i0) : __ldg(ie + i0);
            int4 m = (q.x < NU) ? __ldg(um + i0) : __ldg(im + i0);
            if (m.x) acc.x += v * x.x;
            if (m.y) acc.y += v * x.y;
            if (m.z) acc.z += v * x.z;
            if (m.w) acc.w += v * x.w;
        }
        y[(size_t)r * DV + lane] = acc;
    }
}

// ============ layers 2/3: plain CSR SpMM over compacted row list (pair-unrolled) ============
__global__ void spmm_k(const int* __restrict__ list, const int* __restrict__ cntp,
                       const int* __restrict__ rowptr, const int* __restrict__ bsums,
                       const int* __restrict__ deg, const int2* __restrict__ csr,
                       const float4* __restrict__ x, float4* __restrict__ y) {
    int n16 = *cntp * DV;
    for (int t = blockIdx.x * blockDim.x + threadIdx.x; t < n16;
         t += gridDim.x * blockDim.x) {
        int r = list[t >> 4];
        int lane = t & 15;
        int s = rowptr[r] + __ldg(bsums + (r >> 10));
        int e = s + deg[r];
        float4 acc = make_float4(0.f, 0.f, 0.f, 0.f);
        int j = s;
        for (; j + 2 <= e; j += 2) {
            int2 q0 = __ldg(csr + j);
            int2 q1 = __ldg(csr + j + 1);
            float v0 = __int_as_float(q0.y), v1 = __int_as_float(q1.y);
            float4 x0 = __ldg(x + (size_t)q0.x * DV + lane);
            float4 x1 = __ldg(x + (size_t)q1.x * DV + lane);
            acc.x += v0 * x0.x + v1 * x1.x;
            acc.y += v0 * x0.y + v1 * x1.y;
            acc.z += v0 * x0.z + v1 * x1.z;
            acc.w += v0 * x0.w + v1 * x1.w;
        }
        if (j < e) {
            int2 q = __ldg(csr + j);
            float v = __int_as_float(q.y);
            float4 xv = __ldg(x + (size_t)q.x * DV + lane);
            acc.x += v * xv.x;
            acc.y += v * xv.y;
            acc.z += v * xv.z;
            acc.w += v * xv.w;
        }
        y[(size_t)r * DV + lane] = acc;
    }
}

// ============ single deferred accumulate: out = (init + l1 + l2 + l3) / 4 ============
__global__ void final_acc_k(const float4* __restrict__ l1, const float4* __restrict__ l2,
                            const float4* __restrict__ l3,
                            const int* __restrict__ users, const int* __restrict__ pos,
                            const int* __restrict__ neg, float4* __restrict__ out) {
    int i = blockIdx.x * blockDim.x + threadIdx.x;
    if (i >= 3 * SEC) return;
    int sec = i / SEC;
    int rem = i - sec * SEC;
    int b = rem >> 4;
    int row = (sec == 0) ? users[b] : (sec == 1 ? NU + pos[b] : NU + neg[b]);
    size_t o = (size_t)row * DV + (rem & 15);
    float4 a = out[i], v1 = l1[o], v2 = l2[o], v3 = l3[o];
    float4 r;
    r.x = (a.x + v1.x + v2.x + v3.x) * 0.25f;
    r.y = (a.y + v1.y + v2.y + v3.y) * 0.25f;
    r.z = (a.z + v1.z + v2.z + v3.z) * 0.25f;
    r.w = (a.w + v1.w + v2.w + v3.w) * 0.25f;
    out[i] = r;
}

extern "C" void kernel_launch(void* const* d_in, const int* in_sizes, int n_in,
                              void* d_out, int out_size) {
    const float* ue   = (const float*)d_in[0];
    const float* ie   = (const float*)d_in[1];
    const int*   um   = (const int*)  d_in[2];
    const int*   im   = (const int*)  d_in[3];
    const int*   rows = (const int*)  d_in[4];
    const int*   cols = (const int*)  d_in[5];
    const float* vals = (const float*)d_in[6];
    const int*   users= (const int*)  d_in[7];
    const int*   pos  = (const int*)  d_in[8];
    const int*   neg  = (const int*)  d_in[9];
    int nnz = in_sizes[4];
    int E = nnz / 2;          // undirected pair count (COO is [u->it ; it->u] mirrored)
    float* out = (float*)d_out;

    float *bufA, *bufB, *bufC;
    int2* csr;
    int *rowptr, *bsums, *lists, *blob;
    cudaGetSymbolAddress((void**)&bufA, g_bufA);
    cudaGetSymbolAddress((void**)&bufB, g_bufB);
    cudaGetSymbolAddress((void**)&bufC, g_bufC);
    cudaGetSymbolAddress((void**)&csr, g_scsr);
    cudaGetSymbolAddress((void**)&rowptr, g_rowptr);
    cudaGetSymbolAddress((void**)&bsums, g_bsums);
    cudaGetSymbolAddress((void**)&lists, g_lists);
    cudaGetSymbolAddress((void**)&blob, g_blob);

    int* deg  = blob;
    int* wpos = blob + NN;
    unsigned int* flags = (unsigned int*)(blob + 2 * NN);
    int* cnt  = blob + 3 * NN;

    // lazily-created aux stream + fork/join events (host-side handles only)
    static cudaStream_t sAux = nullptr;
    static cudaEvent_t evFork = nullptr, evJoin = nullptr;
    if (sAux == nullptr) {
        cudaStreamCreateWithFlags(&sAux, cudaStreamNonBlocking);
        cudaEventCreateWithFlags(&evFork, cudaEventDisableTiming);
        cudaEventCreateWithFlags(&evJoin, cudaEventDisableTiming);
    }

    const int TPB = 256;
    const int nBlocks = (NN + TPB - 1) / TPB;
    const int gBlocks = (3 * SEC + TPB - 1) / TPB;
    const int n4 = E / 4;
    const int e4Blocks = (n4 + 1 + TPB - 1) / TPB;
    const int GS = 4096;

    // one memset clears deg, wpos, flags, cnt
    cudaMemsetAsync(blob, 0, (3 * NN + 4) * sizeof(int));
    cudaEventRecord(evFork, 0);
    cudaStreamWaitEvent(sAux, evFork, 0);

    // ---- chain A (default stream): CSR build over first-E symmetric edges ----
    hist_k<<<e4Blocks, TPB>>>((const int4*)rows, (const int4*)cols, deg,
                              n4, rows, cols, E);
    scan1_k<<<NB_SCAN, SCAN_TPB>>>(deg, rowptr, bsums);
    scan2_k<<<1, 1024>>>(bsums);
    scatter_k<<<e4Blocks, TPB>>>((const int4*)rows, (const int4*)cols, (const float4*)vals,
                                 rowptr, bsums, wpos, csr, n4, rows, cols, vals, E);

    // ---- chain B (aux stream): seed + frontiers + compaction ----
    unsigned char* fb = (unsigned char*)flags;
    seed_init_k<<<gBlocks, TPB, 0, sAux>>>((const float4*)ue, (const float4*)ie,
                                           (const int4*)um, (const int4*)im,
                                           users, pos, neg, flags, (float4*)out);
    fpass_k<<<e4Blocks, TPB, 0, sAux>>>((const int4*)rows, (const int4*)cols, fb, 3, 2,
                                        n4, rows, cols, E);
    fpass_k<<<e4Blocks, TPB, 0, sAux>>>((const int4*)rows, (const int4*)cols, fb, 2, 1,
                                        n4, rows, cols, E);
    compact_k<<<nBlocks, TPB, 0, sAux>>>(flags, lists, cnt);
    cudaEventRecord(evJoin, sAux);
    cudaStreamWaitEvent(0, evJoin, 0);

    // ---- 3 SpMM layers (distinct dst buffers), then one deferred accumulate ----
    spmm_fused_k<<<GS, TPB>>>(lists + 0 * NN, cnt + 1, rowptr, bsums, deg, csr,
                              (const float4*)ue, (const float4*)ie,
                              (const int4*)um, (const int4*)im, (float4*)bufA);
    spmm_k<<<GS, TPB>>>(lists + 1 * NN, cnt + 2, rowptr, bsums, deg, csr,
                        (const float4*)bufA, (float4*)bufB);
    spmm_k<<<GS, TPB>>>(lists + 2 * NN, cnt + 3, rowptr, bsums, deg, csr,
                        (const float4*)bufB, (float4*)bufC);
    final_acc_k<<<gBlocks, TPB>>>((const float4*)bufA, (const float4*)bufB,
                                  (const float4*)bufC, users, pos, neg, (float4*)out);
}

// round 7
// speedup vs baseline: 2.6947x; 1.0851x over previous
#include <cuda_runtime.h>
#include <cstdint>

#define NU 400000
#define NN 600000
#define MAXNNZ 1200000
#define DV 16              // float4 words per row (D=64)
#define BATCH 8192
#define SEC (BATCH * DV)

#define SCAN_TPB 256
#define SCAN_ITEMS 4
#define SCAN_CHUNK 1024
#define NB_SCAN ((NN + SCAN_CHUNK - 1) / SCAN_CHUNK)   // 586

// ---- scratch (device globals; allocation is forbidden) ----
__device__ float g_bufA[(size_t)NN * 64];
__device__ float g_bufB[(size_t)NN * 64];
__device__ int2  g_scsr[MAXNNZ];           // packed {col, val}
__device__ int2  g_rowdesc[NN];            // {start, deg}
__device__ int   g_rowlocal[NN];           // block-local exclusive scan of deg
__device__ int   g_wpos[NN];               // absolute write cursors (init by addb_k)
__device__ int   g_bsums[NB_SCAN];
__device__ int   g_lists[2 * NN];          // levels 1..2 (level l at (l-1)*NN)
// single-memset blob: [0,NN)=deg  [NN,2NN)=flags(uint)  [2NN,+4)=cnt
__device__ int   g_blob[2 * NN + 4];

// ================= CSR build (symmetric half-edge, ILP-4) =================
__global__ void hist_k(const int4* __restrict__ r4, const int4* __restrict__ c4,
                       int* __restrict__ deg,
                       int n4, const int* __restrict__ r, const int* __restrict__ c, int E) {
    int i = blockIdx.x * blockDim.x + threadIdx.x;
    if (i < n4) {
        int4 rr = __ldg(r4 + i);
        int4 cc = __ldg(c4 + i);
        atomicAdd(&deg[rr.x], 1); atomicAdd(&deg[cc.x], 1);
        atomicAdd(&deg[rr.y], 1); atomicAdd(&deg[cc.y], 1);
        atomicAdd(&deg[rr.z], 1); atomicAdd(&deg[cc.z], 1);
        atomicAdd(&deg[rr.w], 1); atomicAdd(&deg[cc.w], 1);
    } else if (i == n4) {
        for (int j = n4 * 4; j < E; j++) { atomicAdd(&deg[r[j]], 1); atomicAdd(&deg[c[j]], 1); }
    }
}

__global__ void scan1_k(const int* __restrict__ deg, int* __restrict__ out,
                        int* __restrict__ bsums) {
    __shared__ int sh[SCAN_TPB];
    int base = blockIdx.x * SCAN_CHUNK + threadIdx.x * SCAN_ITEMS;
    int v[SCAN_ITEMS]; int s = 0;
#pragma unroll
    for (int k = 0; k < SCAN_ITEMS; k++) {
        int idx = base + k;
        v[k] = (idx < NN) ? deg[idx] : 0;
        s += v[k];
    }
    sh[threadIdx.x] = s; __syncthreads();
    for (int off = 1; off < SCAN_TPB; off <<= 1) {
        int t = (threadIdx.x >= off) ? sh[threadIdx.x - off] : 0;
        __syncthreads();
        sh[threadIdx.x] += t;
        __syncthreads();
    }
    int excl = sh[threadIdx.x] - s;
    if (threadIdx.x == SCAN_TPB - 1) bsums[blockIdx.x] = sh[SCAN_TPB - 1];
    int run = excl;
#pragma unroll
    for (int k = 0; k < SCAN_ITEMS; k++) {
        int idx = base + k;
        if (idx < NN) out[idx] = run;
        run += v[k];
    }
}

__global__ void scan2_k(int* __restrict__ bsums) {
    __shared__ int sh[1024];
    int v = (threadIdx.x < NB_SCAN) ? bsums[threadIdx.x] : 0;
    sh[threadIdx.x] = v; __syncthreads();
    for (int off = 1; off < 1024; off <<= 1) {
        int t = (threadIdx.x >= off) ? sh[threadIdx.x - off] : 0;
        __syncthreads();
        sh[threadIdx.x] += t;
        __syncthreads();
    }
    if (threadIdx.x < NB_SCAN) bsums[threadIdx.x] = sh[threadIdx.x] - v;  // exclusive
}

// streaming: absolute row starts into wpos (mutable) and rowdesc {start,deg} (stable)
__global__ void addb_k(const int* __restrict__ rowlocal, const int* __restrict__ deg,
                       const int* __restrict__ bsums,
                       int* __restrict__ wpos, int2* __restrict__ rowdesc) {
    int i = blockIdx.x * blockDim.x + threadIdx.x;
    if (i >= NN) return;
    int s = rowlocal[i] + __ldg(bsums + (i >> 10));
    wpos[i] = s;
    rowdesc[i] = make_int2(s, deg[i]);
}

// Symmetric scatter: one atomic + one 8B store per insertion, nothing else.
__global__ void scatter_k(const int4* __restrict__ r4, const int4* __restrict__ c4,
                          const float4* __restrict__ v4,
                          int* __restrict__ wpos, int2* __restrict__ csr,
                          int n4, const int* __restrict__ r, const int* __restrict__ c,
                          const float* __restrict__ v, int E) {
    int i = blockIdx.x * blockDim.x + threadIdx.x;
    if (i < n4) {
        int4 rr = __ldg(r4 + i);
        int4 cc = __ldg(c4 + i);
        float4 vv = __ldg(v4 + i);
        int pr0 = atomicAdd(&wpos[rr.x], 1);
        int pc0 = atomicAdd(&wpos[cc.x], 1);
        int pr1 = atomicAdd(&wpos[rr.y], 1);
        int pc1 = atomicAdd(&wpos[cc.y], 1);
        int pr2 = atomicAdd(&wpos[rr.z], 1);
        int pc2 = atomicAdd(&wpos[cc.z], 1);
        int pr3 = atomicAdd(&wpos[rr.w], 1);
        int pc3 = atomicAdd(&wpos[cc.w], 1);
        csr[pr0] = make_int2(cc.x, __float_as_int(vv.x));
        csr[pc0] = make_int2(rr.x, __float_as_int(vv.x));
        csr[pr1] = make_int2(cc.y, __float_as_int(vv.y));
        csr[pc1] = make_int2(rr.y, __float_as_int(vv.y));
        csr[pr2] = make_int2(cc.z, __float_as_int(vv.z));
        csr[pc2] = make_int2(rr.z, __float_as_int(vv.z));
        csr[pr3] = make_int2(cc.w, __float_as_int(vv.w));
        csr[pc3] = make_int2(rr.w, __float_as_int(vv.w));
    } else if (i == n4) {
        for (int j = n4 * 4; j < E; j++) {
            int rj = r[j], cj = c[j]; float vj = v[j];
            int pr = atomicAdd(&wpos[rj], 1);
            int pc = atomicAdd(&wpos[cj], 1);
            csr[pr] = make_int2(cj, __float_as_int(vj));
            csr[pc] = make_int2(rj, __float_as_int(vj));
        }
    }
}

// ============ seed flags + init output (acc sections = masked source; ego = same) ============
__global__ void seed_init_k(const float4* __restrict__ ue, const float4* __restrict__ ie,
                            const int4* __restrict__ um, const int4* __restrict__ im,
                            const int* __restrict__ users, const int* __restrict__ pos,
                            const int* __restrict__ neg,
                            unsigned int* __restrict__ flags, float4* __restrict__ out) {
    int i = blockIdx.x * blockDim.x + threadIdx.x;
    if (i >= 3 * SEC) return;
    int sec = i / SEC;
    int rem = i - sec * SEC;
    int b = rem >> 4, lane = rem & 15;
    int row = (sec == 0) ? users[b] : (sec == 1 ? NU + pos[b] : NU + neg[b]);
    float4 e; int4 m;
    if (row < NU) { e = ue[row * DV + lane]; m = um[row * DV + lane]; }
    else          { int j = (row - NU) * DV + lane; e = ie[j]; m = im[j]; }
    float4 v;
    v.x = m.x ? e.x : 0.f;
    v.y = m.y ? e.y : 0.f;
    v.z = m.z ? e.z : 0.f;
    v.w = m.w ? e.w : 0.f;
    out[i] = v;
    out[3 * SEC + i] = v;
    if (lane == 0) flags[row] = 0x01010100u;   // bytes 1,2,3 = levels 1,2,3
}

// ============ frontier pass (symmetric, ILP-4): both directions per undirected edge ============
__global__ void fpass_k(const int4* __restrict__ r4, const int4* __restrict__ c4,
                        unsigned char* __restrict__ fb, int inl, int outl,
                        int n4, const int* __restrict__ r, const int* __restrict__ c, int E) {
    int i = blockIdx.x * blockDim.x + threadIdx.x;
    if (i < n4) {
        int4 rr = __ldg(r4 + i);
        int4 cc = __ldg(c4 + i);
        bool r0 = fb[rr.x * 4 + inl], r1 = fb[rr.y * 4 + inl];
        bool r2 = fb[rr.z * 4 + inl], r3 = fb[rr.w * 4 + inl];
        bool c0 = fb[cc.x * 4 + inl], c1 = fb[cc.y * 4 + inl];
        bool c2 = fb[cc.z * 4 + inl], c3 = fb[cc.w * 4 + inl];
        if (r0) fb[cc.x * 4 + outl] = 1;
        if (r1) fb[cc.y * 4 + outl] = 1;
        if (r2) fb[cc.z * 4 + outl] = 1;
        if (r3) fb[cc.w * 4 + outl] = 1;
        if (c0) fb[rr.x * 4 + outl] = 1;
        if (c1) fb[rr.y * 4 + outl] = 1;
        if (c2) fb[rr.z * 4 + outl] = 1;
        if (c3) fb[rr.w * 4 + outl] = 1;
    } else if (i == n4) {
        for (int j = n4 * 4; j < E; j++) {
            if (fb[r[j] * 4 + inl]) fb[c[j] * 4 + outl] = 1;
            if (fb[c[j] * 4 + inl]) fb[r[j] * 4 + outl] = 1;
        }
    }
}

// ============ compact levels 1,2 (warp-aggregated) ============
__global__ void compact_k(const unsigned int* __restrict__ flags,
                          int* __restrict__ lists, int* __restrict__ cnt) {
    int rr = blockIdx.x * blockDim.x + threadIdx.x;
    unsigned int f = (rr < NN) ? flags[rr] : 0u;
    int lane = threadIdx.x & 31;
#pragma unroll
    for (int l = 1; l <= 2; l++) {
        bool p = (f >> (8 * l)) & 1u;
        unsigned int m = __ballot_sync(0xffffffffu, p);
        if (m) {
            int leader = __ffs(m) - 1;
            int base = 0;
            if (lane == leader) base = atomicAdd(cnt + l, __popc(m));
            base = __shfl_sync(0xffffffffu, base, leader);
            if (p) lists[(l - 1) * NN + base + __popc(m & ((1u << lane) - 1u))] = rr;
        }
    }
}

// ============ layer-1 SpMM with on-the-fly masked x0 gather (pair-unrolled) ============
__global__ void spmm_fused_k(const int* __restrict__ list, const int* __restrict__ cntp,
                             const int2* __restrict__ rowdesc, const int2* __restrict__ csr,
                             const float4* __restrict__ ue, const float4* __restrict__ ie,
                             const int4* __restrict__ um, const int4* __restrict__ im,
                             float4* __restrict__ y) {
    int n16 = *cntp * DV;
    for (int t = blockIdx.x * blockDim.x + threadIdx.x; t < n16;
         t += gridDim.x * blockDim.x) {
        int r = list[t >> 4];
        int lane = t & 15;
        int2 rd = __ldg(rowdesc + r);
        int s = rd.x, e = rd.x + rd.y;
        float4 acc = make_float4(0.f, 0.f, 0.f, 0.f);
        int j = s;
        for (; j + 2 <= e; j += 2) {
            int2 q0 = __ldg(csr + j);
            int2 q1 = __ldg(csr + j + 1);
            float v0 = __int_as_float(q0.y), v1 = __int_as_float(q1.y);
            int i0 = (q0.x < NU) ? q0.x * DV + lane : (q0.x - NU) * DV + lane;
            int i1 = (q1.x < NU) ? q1.x * DV + lane : (q1.x - NU) * DV + lane;
            float4 x0 = (q0.x < NU) ? __ldg(ue + i0) : __ldg(ie + i0);
            float4 x1 = (q1.x < NU) ? __ldg(ue + i1) : __ldg(ie + i1);
            int4 m0 = (q0.x < NU) ? __ldg(um + i0) : __ldg(im + i0);
            int4 m1 = (q1.x < NU) ? __ldg(um + i1) : __ldg(im + i1);
            if (m0.x) acc.x += v0 * x0.x;
            if (m0.y) acc.y += v0 * x0.y;
            if (m0.z) acc.z += v0 * x0.z;
            if (m0.w) acc.w += v0 * x0.w;
            if (m1.x) acc.x += v1 * x1.x;
            if (m1.y) acc.y += v1 * x1.y;
            if (m1.z) acc.z += v1 * x1.z;
            if (m1.w) acc.w += v1 * x1.w;
        }
        if (j < e) {
            int2 q = __ldg(csr + j);
            float v = __int_as_float(q.y);
            int i0 = (q.x < NU) ? q.x * DV + lane : (q.x - NU) * DV + lane;
            float4 x = (q.x < NU) ? __ldg(ue + i0) : __ldg(ie + i0);
            int4 m = (q.x < NU) ? __ldg(um + i0) : __ldg(im + i0);
            if (m.x) acc.x += v * x.x;
            if (m.y) acc.y += v * x.y;
            if (m.z) acc.z += v * x.z;
            if (m.w) acc.w += v * x.w;
        }
        y[(size_t)r * DV + lane] = acc;
    }
}

// ============ layer 2: plain CSR SpMM over compacted row list (pair-unrolled) ============
__global__ void spmm_k(const int* __restrict__ list, const int* __restrict__ cntp,
                       const int2* __restrict__ rowdesc, const int2* __restrict__ csr,
                       const float4* __restrict__ x, float4* __restrict__ y) {
    int n16 = *cntp * DV;
    for (int t = blockIdx.x * blockDim.x + threadIdx.x; t < n16;
         t += gridDim.x * blockDim.x) {
        int r = list[t >> 4];
        int lane = t & 15;
        int2 rd = __ldg(rowdesc + r);
        int s = rd.x, e = rd.x + rd.y;
        float4 acc = make_float4(0.f, 0.f, 0.f, 0.f);
        int j = s;
        for (; j + 2 <= e; j += 2) {
            int2 q0 = __ldg(csr + j);
            int2 q1 = __ldg(csr + j + 1);
            float v0 = __int_as_float(q0.y), v1 = __int_as_float(q1.y);
            float4 x0 = __ldg(x + (size_t)q0.x * DV + lane);
            float4 x1 = __ldg(x + (size_t)q1.x * DV + lane);
            acc.x += v0 * x0.x + v1 * x1.x;
            acc.y += v0 * x0.y + v1 * x1.y;
            acc.z += v0 * x0.z + v1 * x1.z;
            acc.w += v0 * x0.w + v1 * x1.w;
        }
        if (j < e) {
            int2 q = __ldg(csr + j);
            float v = __int_as_float(q.y);
            float4 xv = __ldg(x + (size_t)q.x * DV + lane);
            acc.x += v * xv.x;
            acc.y += v * xv.y;
            acc.z += v * xv.z;
            acc.w += v * xv.w;
        }
        y[(size_t)r * DV + lane] = acc;
    }
}

// ============ fused layer-3 SpMM + final accumulate ============
// out[i] = (init + l1 + l2 + spmm3(row)) / 4  computed inline per output slot
__global__ void final_fused_k(const float4* __restrict__ l1, const float4* __restrict__ l2,
                              const int2* __restrict__ rowdesc, const int2* __restrict__ csr,
                              const int* __restrict__ users, const int* __restrict__ pos,
                              const int* __restrict__ neg, float4* __restrict__ out) {
    int i = blockIdx.x * blockDim.x + threadIdx.x;
    if (i >= 3 * SEC) return;
    int sec = i / SEC;
    int rem = i - sec * SEC;
    int b = rem >> 4, lane = rem & 15;
    int row = (sec == 0) ? users[b] : (sec == 1 ? NU + pos[b] : NU + neg[b]);
    size_t o = (size_t)row * DV + lane;
    int2 rd = __ldg(rowdesc + row);
    int s = rd.x, e = rd.x + rd.y;
    float4 acc = make_float4(0.f, 0.f, 0.f, 0.f);
    int j = s;
    for (; j + 2 <= e; j += 2) {
        int2 q0 = __ldg(csr + j);
        int2 q1 = __ldg(csr + j + 1);
        float v0 = __int_as_float(q0.y), v1 = __int_as_float(q1.y);
        float4 x0 = __ldg(l2 + (size_t)q0.x * DV + lane);
        float4 x1 = __ldg(l2 + (size_t)q1.x * DV + lane);
        acc.x += v0 * x0.x + v1 * x1.x;
        acc.y += v0 * x0.y + v1 * x1.y;
        acc.z += v0 * x0.z + v1 * x1.z;
        acc.w += v0 * x0.w + v1 * x1.w;
    }
    if (j < e) {
        int2 q = __ldg(csr + j);
        float v = __int_as_float(q.y);
        float4 xv = __ldg(l2 + (size_t)q.x * DV + lane);
        acc.x += v * xv.x;
        acc.y += v * xv.y;
        acc.z += v * xv.z;
        acc.w += v * xv.w;
    }
    float4 a = out[i], v1 = l1[o], v2 = l2[o];
    float4 r;
    r.x = (a.x + v1.x + v2.x + acc.x) * 0.25f;
    r.y = (a.y + v1.y + v2.y + acc.y) * 0.25f;
    r.z = (a.z + v1.z + v2.z + acc.z) * 0.25f;
    r.w = (a.w + v1.w + v2.w + acc.w) * 0.25f;
    out[i] = r;
}

extern "C" void kernel_launch(void* const* d_in, const int* in_sizes, int n_in,
                              void* d_out, int out_size) {
    const float* ue   = (const float*)d_in[0];
    const float* ie   = (const float*)d_in[1];
    const int*   um   = (const int*)  d_in[2];
    const int*   im   = (const int*)  d_in[3];
    const int*   rows = (const int*)  d_in[4];
    const int*   cols = (const int*)  d_in[5];
    const float* vals = (const float*)d_in[6];
    const int*   users= (const int*)  d_in[7];
    const int*   pos  = (const int*)  d_in[8];
    const int*   neg  = (const int*)  d_in[9];
    int nnz = in_sizes[4];
    int E = nnz / 2;          // undirected pair count (COO is [u->it ; it->u] mirrored)
    float* out = (float*)d_out;

    float *bufA, *bufB;
    int2 *csr, *rowdesc;
    int *rowlocal, *wpos, *bsums, *lists, *blob;
    cudaGetSymbolAddress((void**)&bufA, g_bufA);
    cudaGetSymbolAddress((void**)&bufB, g_bufB);
    cudaGetSymbolAddress((void**)&csr, g_scsr);
    cudaGetSymbolAddress((void**)&rowdesc, g_rowdesc);
    cudaGetSymbolAddress((void**)&rowlocal, g_rowlocal);
    cudaGetSymbolAddress((void**)&wpos, g_wpos);
    cudaGetSymbolAddress((void**)&bsums, g_bsums);
    cudaGetSymbolAddress((void**)&lists, g_lists);
    cudaGetSymbolAddress((void**)&blob, g_blob);

    int* deg = blob;
    unsigned int* flags = (unsigned int*)(blob + NN);
    int* cnt = blob + 2 * NN;

    // lazily-created aux stream + fork/join events (host-side handles only)
    static cudaStream_t sAux = nullptr;
    static cudaEvent_t evFork = nullptr, evJoin = nullptr;
    if (sAux == nullptr) {
        cudaStreamCreateWithFlags(&sAux, cudaStreamNonBlocking);
        cudaEventCreateWithFlags(&evFork, cudaEventDisableTiming);
        cudaEventCreateWithFlags(&evJoin, cudaEventDisableTiming);
    }

    const int TPB = 256;
    const int nBlocks = (NN + TPB - 1) / TPB;
    const int gBlocks = (3 * SEC + TPB - 1) / TPB;
    const int n4 = E / 4;
    const int e4Blocks = (n4 + 1 + TPB - 1) / TPB;
    const int GS = 4096;

    // one memset clears deg, flags, cnt
    cudaMemsetAsync(blob, 0, (2 * NN + 4) * sizeof(int));
    cudaEventRecord(evFork, 0);
    cudaStreamWaitEvent(sAux, evFork, 0);

    // ---- chain A (default stream): CSR build over first-E symmetric edges ----
    hist_k<<<e4Blocks, TPB>>>((const int4*)rows, (const int4*)cols, deg,
                              n4, rows, cols, E);
    scan1_k<<<NB_SCAN, SCAN_TPB>>>(deg, rowlocal, bsums);
    scan2_k<<<1, 1024>>>(bsums);
    addb_k<<<nBlocks, TPB>>>(rowlocal, deg, bsums, wpos, rowdesc);
    scatter_k<<<e4Blocks, TPB>>>((const int4*)rows, (const int4*)cols, (const float4*)vals,
                                 wpos, csr, n4, rows, cols, vals, E);

    // ---- chain B (aux stream): seed + frontiers + compaction ----
    unsigned char* fb = (unsigned char*)flags;
    seed_init_k<<<gBlocks, TPB, 0, sAux>>>((const float4*)ue, (const float4*)ie,
                                           (const int4*)um, (const int4*)im,
                                           users, pos, neg, flags, (float4*)out);
    fpass_k<<<e4Blocks, TPB, 0, sAux>>>((const int4*)rows, (const int4*)cols, fb, 3, 2,
                                        n4, rows, cols, E);
    fpass_k<<<e4Blocks, TPB, 0, sAux>>>((const int4*)rows, (const int4*)cols, fb, 2, 1,
                                        n4, rows, cols, E);
    compact_k<<<nBlocks, TPB, 0, sAux>>>(flags, lists, cnt);
    cudaEventRecord(evJoin, sAux);
    cudaStreamWaitEvent(0, evJoin, 0);

    // ---- layers 1,2 then fused layer-3 + accumulate ----
    spmm_fused_k<<<GS, TPB>>>(lists + 0 * NN, cnt + 1, rowdesc, csr,
                              (const float4*)ue, (const float4*)ie,
                              (const int4*)um, (const int4*)im, (float4*)bufA);
    spmm_k<<<GS, TPB>>>(lists + 1 * NN, cnt + 2, rowdesc, csr,
                        (const float4*)bufA, (float4*)bufB);
    final_fused_k<<<gBlocks, TPB>>>((const float4*)bufA, (const float4*)bufB,
                                    rowdesc, csr, users, pos, neg, (float4*)out);
}

// round 9
// speedup vs baseline: 3.6226x; 1.3443x over previous
#include <cuda_runtime.h>
#include <cstdint>

#define NU 400000
#define NN 600000
#define MAXNNZ 1200000
#define DV 16              // float4 words per row (D=64)
#define BATCH 8192
#define SEC (BATCH * DV)

#define SCAN_TPB 256
#define SCAN_ITEMS 4
#define SCAN_CHUNK 1024
#define NB_SCAN ((NN + SCAN_CHUNK - 1) / SCAN_CHUNK)   // 586

// ---- scratch (device globals; allocation is forbidden) ----
__device__ float g_bufA[(size_t)NN * 64];
__device__ float g_bufB[(size_t)NN * 64];
__device__ int2  g_scsr[MAXNNZ];           // packed {col, val}
__device__ int2  g_rowdesc[NN];            // {start, deg}
__device__ int   g_wpos[NN];               // absolute write cursors
__device__ int   g_sizes[NN];              // per-row embedding size (prefix-mask sum)
__device__ int   g_lists[2 * NN];          // levels 1..2 (level l at (l-1)*NN)
// single-memset blob: [0,NN)=deg [NN,2NN)=flags(uint) [2NN,+4)=cnt [2NN+4,+NB_SCAN)=scan state
__device__ int   g_blob[2 * NN + 4 + NB_SCAN];

// ================= per-row sizes from prefix masks (streaming, overlapped) =================
__global__ void sizes_k(const int4* __restrict__ um, const int4* __restrict__ im,
                        int* __restrict__ sizes) {
    int t = blockIdx.x * blockDim.x + threadIdx.x;
    if (t >= NN * DV) return;
    int r = t >> 4, lane = t & 15;
    int4 m = (r < NU) ? __ldg(um + r * DV + lane) : __ldg(im + (r - NU) * DV + lane);
    int s = m.x + m.y + m.z + m.w;
    s += __shfl_down_sync(0xffffffffu, s, 8, 16);
    s += __shfl_down_sync(0xffffffffu, s, 4, 16);
    s += __shfl_down_sync(0xffffffffu, s, 2, 16);
    s += __shfl_down_sync(0xffffffffu, s, 1, 16);
    if (lane == 0) sizes[r] = s;
}

// ================= CSR build =================
__global__ void hist_k(const int4* __restrict__ r4, const int4* __restrict__ c4,
                       int* __restrict__ deg,
                       int n4, const int* __restrict__ r, const int* __restrict__ c, int E) {
    int i = blockIdx.x * blockDim.x + threadIdx.x;
    if (i < n4) {
        int4 rr = __ldg(r4 + i);
        int4 cc = __ldg(c4 + i);
        atomicAdd(&deg[rr.x], 1); atomicAdd(&deg[cc.x], 1);
        atomicAdd(&deg[rr.y], 1); atomicAdd(&deg[cc.y], 1);
        atomicAdd(&deg[rr.z], 1); atomicAdd(&deg[cc.z], 1);
        atomicAdd(&deg[rr.w], 1); atomicAdd(&deg[cc.w], 1);
    } else if (i == n4) {
        for (int j = n4 * 4; j < E; j++) { atomicAdd(&deg[r[j]], 1); atomicAdd(&deg[c[j]], 1); }
    }
}

// Single-pass decoupled-lookback scan: deg -> wpos (cursors) + rowdesc {start,deg}
__global__ void scan_k(const int* __restrict__ deg, int* __restrict__ wpos,
                       int2* __restrict__ rowdesc, unsigned int* state) {
    __shared__ int sh[SCAN_TPB];
    __shared__ int sbase;
    int bid = blockIdx.x;
    int base = bid * SCAN_CHUNK + threadIdx.x * SCAN_ITEMS;
    int v[SCAN_ITEMS]; int s = 0;
#pragma unroll
    for (int k = 0; k < SCAN_ITEMS; k++) {
        int idx = base + k;
        v[k] = (idx < NN) ? deg[idx] : 0;
        s += v[k];
    }
    sh[threadIdx.x] = s; __syncthreads();
    for (int off = 1; off < SCAN_TPB; off <<= 1) {
        int t = (threadIdx.x >= off) ? sh[threadIdx.x - off] : 0;
        __syncthreads();
        sh[threadIdx.x] += t;
        __syncthreads();
    }
    if (threadIdx.x == 0) {
        unsigned int total = (unsigned int)sh[SCAN_TPB - 1];
        if (bid == 0) {
            atomicExch(&state[0], (2u << 30) | total);
            sbase = 0;
        } else {
            atomicExch(&state[bid], (1u << 30) | total);
            unsigned int excl = 0;
            int j = bid - 1;
            while (true) {
                unsigned int st;
                do { st = atomicAdd(&state[j], 0u); } while ((st >> 30) == 0u);
                excl += st & 0x3FFFFFFFu;
                if ((st >> 30) == 2u) break;
                j--;
            }
            atomicExch(&state[bid], (2u << 30) | (excl + total));
            sbase = (int)excl;
        }
    }
    __syncthreads();
    int run = sbase + (sh[threadIdx.x] - s);
#pragma unroll
    for (int k = 0; k < SCAN_ITEMS; k++) {
        int idx = base + k;
        if (idx < NN) { wpos[idx] = run; rowdesc[idx] = make_int2(run, v[k]); }
        run += v[k];
    }
}

// Frontier-filtered symmetric scatter: insert only for endpoints with nonzero flags.
__global__ void scatter_k(const int4* __restrict__ r4, const int4* __restrict__ c4,
                          const float4* __restrict__ v4,
                          const unsigned int* __restrict__ flags,
                          int* __restrict__ wpos, int2* __restrict__ csr,
                          int n4, const int* __restrict__ r, const int* __restrict__ c,
                          const float* __restrict__ v, int E) {
    int i = blockIdx.x * blockDim.x + threadIdx.x;
    if (i < n4) {
        int4 rr = __ldg(r4 + i);
        int4 cc = __ldg(c4 + i);
        float4 vv = __ldg(v4 + i);
        unsigned int fr0 = __ldg(flags + rr.x), fc0 = __ldg(flags + cc.x);
        unsigned int fr1 = __ldg(flags + rr.y), fc1 = __ldg(flags + cc.y);
        unsigned int fr2 = __ldg(flags + rr.z), fc2 = __ldg(flags + cc.z);
        unsigned int fr3 = __ldg(flags + rr.w), fc3 = __ldg(flags + cc.w);
        if (fr0) { int p = atomicAdd(&wpos[rr.x], 1); csr[p] = make_int2(cc.x, __float_as_int(vv.x)); }
        if (fc0) { int p = atomicAdd(&wpos[cc.x], 1); csr[p] = make_int2(rr.x, __float_as_int(vv.x)); }
        if (fr1) { int p = atomicAdd(&wpos[rr.y], 1); csr[p] = make_int2(cc.y, __float_as_int(vv.y)); }
        if (fc1) { int p = atomicAdd(&wpos[cc.y], 1); csr[p] = make_int2(rr.y, __float_as_int(vv.y)); }
        if (fr2) { int p = atomicAdd(&wpos[rr.z], 1); csr[p] = make_int2(cc.z, __float_as_int(vv.z)); }
        if (fc2) { int p = atomicAdd(&wpos[cc.z], 1); csr[p] = make_int2(rr.z, __float_as_int(vv.z)); }
        if (fr3) { int p = atomicAdd(&wpos[rr.w], 1); csr[p] = make_int2(cc.w, __float_as_int(vv.w)); }
        if (fc3) { int p = atomicAdd(&wpos[cc.w], 1); csr[p] = make_int2(rr.w, __float_as_int(vv.w)); }
    } else if (i == n4) {
        for (int j = n4 * 4; j < E; j++) {
            int rj = r[j], cj = c[j]; float vj = v[j];
            if (__ldg(flags + rj)) { int p = atomicAdd(&wpos[rj], 1); csr[p] = make_int2(cj, __float_as_int(vj)); }
            if (__ldg(flags + cj)) { int p = atomicAdd(&wpos[cj], 1); csr[p] = make_int2(rj, __float_as_int(vj)); }
        }
    }
}

// ============ seed flags + init output ============
__global__ void seed_init_k(const float4* __restrict__ ue, const float4* __restrict__ ie,
                            const int4* __restrict__ um, const int4* __restrict__ im,
                            const int* __restrict__ users, const int* __restrict__ pos,
                            const int* __restrict__ neg,
                            unsigned int* __restrict__ flags, float4* __restrict__ out) {
    int i = blockIdx.x * blockDim.x + threadIdx.x;
    if (i >= 3 * SEC) return;
    int sec = i / SEC;
    int rem = i - sec * SEC;
    int b = rem >> 4, lane = rem & 15;
    int row = (sec == 0) ? users[b] : (sec == 1 ? NU + pos[b] : NU + neg[b]);
    float4 e; int4 m;
    if (row < NU) { e = ue[row * DV + lane]; m = um[row * DV + lane]; }
    else          { int j = (row - NU) * DV + lane; e = ie[j]; m = im[j]; }
    float4 v;
    v.x = m.x ? e.x : 0.f;
    v.y = m.y ? e.y : 0.f;
    v.z = m.z ? e.z : 0.f;
    v.w = m.w ? e.w : 0.f;
    out[i] = v;
    out[3 * SEC + i] = v;
    if (lane == 0) flags[row] = 0x01010100u;   // bytes 1,2,3 = levels 1,2,3
}

// ============ frontier pass (symmetric, ILP-4) ============
__global__ void fpass_k(const int4* __restrict__ r4, const int4* __restrict__ c4,
                        unsigned char* __restrict__ fb, int inl, int outl,
                        int n4, const int* __restrict__ r, const int* __restrict__ c, int E) {
    int i = blockIdx.x * blockDim.x + threadIdx.x;
    if (i < n4) {
        int4 rr = __ldg(r4 + i);
        int4 cc = __ldg(c4 + i);
        bool r0 = fb[rr.x * 4 + inl], r1 = fb[rr.y * 4 + inl];
        bool r2 = fb[rr.z * 4 + inl], r3 = fb[rr.w * 4 + inl];
        bool c0 = fb[cc.x * 4 + inl], c1 = fb[cc.y * 4 + inl];
        bool c2 = fb[cc.z * 4 + inl], c3 = fb[cc.w * 4 + inl];
        if (r0) fb[cc.x * 4 + outl] = 1;
        if (r1) fb[cc.y * 4 + outl] = 1;
        if (r2) fb[cc.z * 4 + outl] = 1;
        if (r3) fb[cc.w * 4 + outl] = 1;
        if (c0) fb[rr.x * 4 + outl] = 1;
        if (c1) fb[rr.y * 4 + outl] = 1;
        if (c2) fb[rr.z * 4 + outl] = 1;
        if (c3) fb[rr.w * 4 + outl] = 1;
    } else if (i == n4) {
        for (int j = n4 * 4; j < E; j++) {
            if (fb[r[j] * 4 + inl]) fb[c[j] * 4 + outl] = 1;
            if (fb[c[j] * 4 + inl]) fb[r[j] * 4 + outl] = 1;
        }
    }
}

// ============ compact levels 1,2 (warp-aggregated) ============
__global__ void compact_k(const unsigned int* __restrict__ flags,
                          int* __restrict__ lists, int* __restrict__ cnt) {
    int rr = blockIdx.x * blockDim.x + threadIdx.x;
    unsigned int f = (rr < NN) ? flags[rr] : 0u;
    int lane = threadIdx.x & 31;
#pragma unroll
    for (int l = 1; l <= 2; l++) {
        bool p = (f >> (8 * l)) & 1u;
        unsigned int m = __ballot_sync(0xffffffffu, p);
        if (m) {
            int leader = __ffs(m) - 1;
            int base = 0;
            if (lane == leader) base = atomicAdd(cnt + l, __popc(m));
            base = __shfl_sync(0xffffffffu, base, leader);
            if (p) lists[(l - 1) * NN + base + __popc(m & ((1u << lane) - 1u))] = rr;
        }
    }
}

// ============ layer-1 SpMM: masked x0 gather via per-row sizes ============
__global__ void spmm_fused_k(const int* __restrict__ list, const int* __restrict__ cntp,
                             const int2* __restrict__ rowdesc, const int2* __restrict__ csr,
                             const int* __restrict__ sizes,
                             const float4* __restrict__ ue, const float4* __restrict__ ie,
                             float4* __restrict__ y) {
    int n16 = *cntp * DV;
    for (int t = blockIdx.x * blockDim.x + threadIdx.x; t < n16;
         t += gridDim.x * blockDim.x) {
        int r = list[t >> 4];
        int lane = t & 15;
        int k = lane << 2;
        int2 rd = __ldg(rowdesc + r);
        int s = rd.x, e = rd.x + rd.y;
        float4 acc = make_float4(0.f, 0.f, 0.f, 0.f);
        int j = s;
        for (; j + 2 <= e; j += 2) {
            int2 q0 = __ldg(csr + j);
            int2 q1 = __ldg(csr + j + 1);
            float v0 = __int_as_float(q0.y), v1 = __int_as_float(q1.y);
            int i0 = (q0.x < NU) ? q0.x * DV + lane : (q0.x - NU) * DV + lane;
            int i1 = (q1.x < NU) ? q1.x * DV + lane : (q1.x - NU) * DV + lane;
            float4 x0 = (q0.x < NU) ? __ldg(ue + i0) : __ldg(ie + i0);
            float4 x1 = (q1.x < NU) ? __ldg(ue + i1) : __ldg(ie + i1);
            int s0 = __ldg(sizes + q0.x);
            int s1 = __ldg(sizes + q1.x);
            if (k + 0 < s0) acc.x += v0 * x0.x;
            if (k + 1 < s0) acc.y += v0 * x0.y;
            if (k + 2 < s0) acc.z += v0 * x0.z;
            if (k + 3 < s0) acc.w += v0 * x0.w;
            if (k + 0 < s1) acc.x += v1 * x1.x;
            if (k + 1 < s1) acc.y += v1 * x1.y;
            if (k + 2 < s1) acc.z += v1 * x1.z;
            if (k + 3 < s1) acc.w += v1 * x1.w;
        }
        if (j < e) {
            int2 q = __ldg(csr + j);
            float v = __int_as_float(q.y);
            int i0 = (q.x < NU) ? q.x * DV + lane : (q.x - NU) * DV + lane;
            float4 x = (q.x < NU) ? __ldg(ue + i0) : __ldg(ie + i0);
            int s0 = __ldg(sizes + q.x);
            if (k + 0 < s0) acc.x += v * x.x;
            if (k + 1 < s0) acc.y += v * x.y;
            if (k + 2 < s0) acc.z += v * x.z;
            if (k + 3 < s0) acc.w += v * x.w;
        }
        y[(size_t)r * DV + lane] = acc;
    }
}

// ============ layer 2: plain CSR SpMM ============
__global__ void spmm_k(const int* __restrict__ list, const int* __restrict__ cntp,
                       const int2* __restrict__ rowdesc, const int2* __restrict__ csr,
                       const float4* __restrict__ x, float4* __restrict__ y) {
    int n16 = *cntp * DV;
    for (int t = blockIdx.x * blockDim.x + threadIdx.x; t < n16;
         t += gridDim.x * blockDim.x) {
        int r = list[t >> 4];
        int lane = t & 15;
        int2 rd = __ldg(rowdesc + r);
        int s = rd.x, e = rd.x + rd.y;
        float4 acc = make_float4(0.f, 0.f, 0.f, 0.f);
        int j = s;
        for (; j + 2 <= e; j += 2) {
            int2 q0 = __ldg(csr + j);
            int2 q1 = __ldg(csr + j + 1);
            float v0 = __int_as_float(q0.y), v1 = __int_as_float(q1.y);
            float4 x0 = __ldg(x + (size_t)q0.x * DV + lane);
            float4 x1 = __ldg(x + (size_t)q1.x * DV + lane);
            acc.x += v0 * x0.x + v1 * x1.x;
            acc.y += v0 * x0.y + v1 * x1.y;
            acc.z += v0 * x0.z + v1 * x1.z;
            acc.w += v0 * x0.w + v1 * x1.w;
        }
        if (j < e) {
            int2 q = __ldg(csr + j);
            float v = __int_as_float(q.y);
            float4 xv = __ldg(x + (size_t)q.x * DV + lane);
            acc.x += v * xv.x;
            acc.y += v * xv.y;
            acc.z += v * xv.z;
            acc.w += v * xv.w;
        }
        y[(size_t)r * DV + lane] = acc;
    }
}

// ============ fused layer-3 SpMM + final accumulate ============
__global__ void final_fused_k(const float4* __restrict__ l1, const float4* __restrict__ l2,
                              const int2* __restrict__ rowdesc, const int2* __restrict__ csr,
                              const int* __restrict__ users, const int* __restrict__ pos,
                              const int* __restrict__ neg, float4* __restrict__ out) {
    int i = blockIdx.x * blockDim.x + threadIdx.x;
    if (i >= 3 * SEC) return;
    int sec = i / SEC;
    int rem = i - sec * SEC;
    int b = rem >> 4, lane = rem & 15;
    int row = (sec == 0) ? users[b] : (sec == 1 ? NU + pos[b] : NU + neg[b]);
    size_t o = (size_t)row * DV + lane;
    int2 rd = __ldg(rowdesc + row);
    int s = rd.x, e = rd.x + rd.y;
    float4 acc = make_float4(0.f, 0.f, 0.f, 0.f);
    int j = s;
    for (; j + 2 <= e; j += 2) {
        int2 q0 = __ldg(csr + j);
        int2 q1 = __ldg(csr + j + 1);
        float v0 = __int_as_float(q0.y), v1 = __int_as_float(q1.y);
        float4 x0 = __ldg(l2 + (size_t)q0.x * DV + lane);
        float4 x1 = __ldg(l2 + (size_t)q1.x * DV + lane);
        acc.x += v0 * x0.x + v1 * x1.x;
        acc.y += v0 * x0.y + v1 * x1.y;
        acc.z += v0 * x0.z + v1 * x1.z;
        acc.w += v0 * x0.w + v1 * x1.w;
    }
    if (j < e) {
        int2 q = __ldg(csr + j);
        float v = __int_as_float(q.y);
        float4 xv = __ldg(l2 + (size_t)q.x * DV + lane);
        acc.x += v * xv.x;
        acc.y += v * xv.y;
        acc.z += v * xv.z;
        acc.w += v * xv.w;
    }
    float4 a = out[i], v1 = l1[o], v2 = l2[o];
    float4 r;
    r.x = (a.x + v1.x + v2.x + acc.x) * 0.25f;
    r.y = (a.y + v1.y + v2.y + acc.y) * 0.25f;
    r.z = (a.z + v1.z + v2.z + acc.z) * 0.25f;
    r.w = (a.w + v1.w + v2.w + acc.w) * 0.25f;
    out[i] = r;
}

extern "C" void kernel_launch(void* const* d_in, const int* in_sizes, int n_in,
                              void* d_out, int out_size) {
    const float* ue   = (const float*)d_in[0];
    const float* ie   = (const float*)d_in[1];
    const int*   um   = (const int*)  d_in[2];
    const int*   im   = (const int*)  d_in[3];
    const int*   rows = (const int*)  d_in[4];
    const int*   cols = (const int*)  d_in[5];
    const float* vals = (const float*)d_in[6];
    const int*   users= (const int*)  d_in[7];
    const int*   pos  = (const int*)  d_in[8];
    const int*   neg  = (const int*)  d_in[9];
    int nnz = in_sizes[4];
    int E = nnz / 2;          // COO is mirrored [u->it ; it->u]
    float* out = (float*)d_out;

    float *bufA, *bufB;
    int2 *csr, *rowdesc;
    int *wpos, *sizes, *lists, *blob;
    cudaGetSymbolAddress((void**)&bufA, g_bufA);
    cudaGetSymbolAddress((void**)&bufB, g_bufB);
    cudaGetSymbolAddress((void**)&csr, g_scsr);
    cudaGetSymbolAddress((void**)&rowdesc, g_rowdesc);
    cudaGetSymbolAddress((void**)&wpos, g_wpos);
    cudaGetSymbolAddress((void**)&sizes, g_sizes);
    cudaGetSymbolAddress((void**)&lists, g_lists);
    cudaGetSymbolAddress((void**)&blob, g_blob);

    int* deg = blob;
    unsigned int* flags = (unsigned int*)(blob + NN);
    int* cnt = blob + 2 * NN;
    unsigned int* state = (unsigned int*)(blob + 2 * NN + 4);

    // lazily-created aux streams + events (host-side handles only)
    static cudaStream_t s1 = nullptr, s2 = nullptr;
    static cudaEvent_t evFork = nullptr, evFlags = nullptr, evJoin = nullptr, evSizes = nullptr;
    if (s1 == nullptr) {
        cudaStreamCreateWithFlags(&s1, cudaStreamNonBlocking);
        cudaStreamCreateWithFlags(&s2, cudaStreamNonBlocking);
        cudaEventCreateWithFlags(&evFork, cudaEventDisableTiming);
        cudaEventCreateWithFlags(&evFlags, cudaEventDisableTiming);
        cudaEventCreateWithFlags(&evJoin, cudaEventDisableTiming);
        cudaEventCreateWithFlags(&evSizes, cudaEventDisableTiming);
    }

    const int TPB = 256;
    const int nBlocks = (NN + TPB - 1) / TPB;
    const int gBlocks = (3 * SEC + TPB - 1) / TPB;
    const int n4 = E / 4;
    const int e4Blocks = (n4 + 1 + TPB - 1) / TPB;
    const int szBlocks = (NN * DV + TPB - 1) / TPB;
    const int GS = 4096;

    // LEGAL capture fork: record fork event on origin stream FIRST, then both
    // side streams begin with a wait on it before launching any work.
    cudaEventRecord(evFork, 0);
    cudaStreamWaitEvent(s1, evFork, 0);
    cudaStreamWaitEvent(s2, evFork, 0);

    // chain C (s2): per-row sizes — independent, streaming, fully overlapped
    sizes_k<<<szBlocks, TPB, 0, s2>>>((const int4*)um, (const int4*)im, sizes);
    cudaEventRecord(evSizes, s2);

    // ---- chain A (default): memset + hist + fused scan ----
    cudaMemsetAsync(blob, 0, (2 * NN + 4 + NB_SCAN) * sizeof(int));
    hist_k<<<e4Blocks, TPB>>>((const int4*)rows, (const int4*)cols, deg,
                              n4, rows, cols, E);
    scan_k<<<NB_SCAN, SCAN_TPB>>>(deg, wpos, rowdesc, state);

    // ---- chain B (s1): seed + frontier passes + compaction ----
    // NOTE: seed_init writes flags which the memset on stream 0 also touches;
    // order seed after memset via event.
    unsigned char* fb = (unsigned char*)flags;
    seed_init_k<<<gBlocks, TPB, 0, s1>>>((const float4*)ue, (const float4*)ie,
                                         (const int4*)um, (const int4*)im,
                                         users, pos, neg, flags, (float4*)out);
    fpass_k<<<e4Blocks, TPB, 0, s1>>>((const int4*)rows, (const int4*)cols, fb, 3, 2,
                                      n4, rows, cols, E);
    fpass_k<<<e4Blocks, TPB, 0, s1>>>((const int4*)rows, (const int4*)cols, fb, 2, 1,
                                      n4, rows, cols, E);
    cudaEventRecord(evFlags, s1);
    compact_k<<<nBlocks, TPB, 0, s1>>>(flags, lists, cnt);
    cudaEventRecord(evJoin, s1);

    // scatter needs flags (frontier-filtered) + scan cursors
    cudaStreamWaitEvent(0, evFlags, 0);
    scatter_k<<<e4Blocks, TPB>>>((const int4*)rows, (const int4*)cols, (const float4*)vals,
                                 flags, wpos, csr, n4, rows, cols, vals, E);

    cudaStreamWaitEvent(0, evJoin, 0);
    cudaStreamWaitEvent(0, evSizes, 0);

    // ---- layers 1,2 then fused layer-3 + accumulate ----
    spmm_fused_k<<<GS, TPB>>>(lists + 0 * NN, cnt + 1, rowdesc, csr, sizes,
                              (const float4*)ue, (const float4*)ie, (float4*)bufA);
    spmm_k<<<GS, TPB>>>(lists + 1 * NN, cnt + 2, rowdesc, csr,
                        (const float4*)bufA, (float4*)bufB);
    final_fused_k<<<gBlocks, TPB>>>((const float4*)bufA, (const float4*)bufB,
                                    rowdesc, csr, users, pos, neg, (float4*)out);
}